// round 2
// baseline (speedup 1.0000x reference)
#include <cuda_runtime.h>
#include <cstdint>

// Problem constants (sized for this dataset)
#define MAXN 50000
#define MAXE 800000
#define MAXEE (MAXN + MAXE)
#define F 128          // feature dim (Din = HID = 128)
#define NHEAD 2
#define CDIM 64
#define NEG 0.2f

// ---------------- scratch (device globals; no allocation) ----------------
__device__ float g_h[(size_t)MAXN * F];     // h = X @ W for current layer
__device__ float g_feat[(size_t)MAXN * F];  // layer activations
__device__ float g_out[(size_t)MAXN * F];   // aggregation accumulator
__device__ float g_als[MAXN * NHEAD];       // alpha_src logits per node
__device__ float g_ald[MAXN * NHEAD];       // alpha_dst logits per node
__device__ unsigned g_segmax[MAXN * NHEAD]; // ordered-key max per (node, head)
__device__ float g_segsum[MAXN * NHEAD];    // softmax denominator
__device__ int g_src[MAXEE];
__device__ int g_dst[MAXEE];

// ---------------- helpers ----------------
__device__ __forceinline__ unsigned fkey(float f) {
    unsigned u = __float_as_uint(f);
    return (u & 0x80000000u) ? ~u : (u | 0x80000000u);
}
__device__ __forceinline__ float funkey(unsigned k) {
    unsigned u = (k & 0x80000000u) ? (k & 0x7fffffffu) : ~k;
    return __uint_as_float(u);
}
__device__ __forceinline__ float leaky(float x) { return x > 0.f ? x : NEG * x; }

// ---------------- kernels ----------------

// edge_index is int32 (JAX default config demotes int64 -> int32).
// Copy to g_src/g_dst and append self loops.
__global__ void k_build_edges(const int* __restrict__ ei, int E, int N) {
    int i = blockIdx.x * blockDim.x + threadIdx.x;
    int EE = E + N;
    if (i >= EE) return;
    if (i < E) {
        g_src[i] = ei[i];
        g_dst[i] = ei[E + i];
    } else {
        g_src[i] = i - E;
        g_dst[i] = i - E;
    }
}

// H = A[N,128] @ W[128,128].  Block: 256 thr, 64 rows. Warp w -> rows w*8..+8,
// lane l -> cols 4l..4l+3. Whole W staged in SMEM.
__global__ void k_gemm128(const float* __restrict__ A, const float* __restrict__ W,
                          float* __restrict__ Hout, int N) {
    extern __shared__ float sm[];
    float* Xs = sm;              // 64*128
    float* Ws = sm + 64 * F;     // 128*128
    int tid = threadIdx.x;
    int warp = tid >> 5, lane = tid & 31;
    int row0 = blockIdx.x * 64;

    const float4* W4 = (const float4*)W;
    float4* Ws4 = (float4*)Ws;
#pragma unroll
    for (int i = 0; i < 16; i++) Ws4[tid + i * 256] = W4[tid + i * 256];

    const float4* A4 = (const float4*)A;
    float4* Xs4 = (float4*)Xs;
#pragma unroll
    for (int i = 0; i < 8; i++) {
        int idx = tid + i * 256;             // float4 index in 64x32 tile
        int r = row0 + (idx >> 5);
        Xs4[idx] = (r < N) ? A4[(size_t)r * 32 + (idx & 31)]
                           : make_float4(0.f, 0.f, 0.f, 0.f);
    }
    __syncthreads();

    float4 acc[8];
#pragma unroll
    for (int i = 0; i < 8; i++) acc[i] = make_float4(0.f, 0.f, 0.f, 0.f);
    int rbase = warp * 8;

#pragma unroll 4
    for (int k = 0; k < F; k++) {
        float4 w = Ws4[k * 32 + lane];
#pragma unroll
        for (int r = 0; r < 8; r++) {
            float xv = Xs[(rbase + r) * F + k];
            acc[r].x += xv * w.x;
            acc[r].y += xv * w.y;
            acc[r].z += xv * w.z;
            acc[r].w += xv * w.w;
        }
    }
#pragma unroll
    for (int r = 0; r < 8; r++) {
        int rr = row0 + rbase + r;
        if (rr < N) ((float4*)Hout)[(size_t)rr * 32 + lane] = acc[r];
    }
}

// Per-node attention logits: al_src[n,h] = sum_c h[n,h,c]*a_src[h,c] (flat 128 dot).
// One warp per node; lanes 0-15 reduce head 0, lanes 16-31 head 1.
__global__ void k_attn(const float* __restrict__ a_src, const float* __restrict__ a_dst, int N) {
    int gw = (blockIdx.x * blockDim.x + threadIdx.x) >> 5;
    if (gw >= N) return;
    int lane = threadIdx.x & 31;
    float4 hv = ((const float4*)g_h)[(size_t)gw * 32 + lane];
    float4 as = __ldg(((const float4*)a_src) + lane);
    float4 ad = __ldg(((const float4*)a_dst) + lane);
    float s = hv.x * as.x + hv.y * as.y + hv.z * as.z + hv.w * as.w;
    float d = hv.x * ad.x + hv.y * ad.y + hv.z * ad.z + hv.w * ad.w;
#pragma unroll
    for (int o = 8; o; o >>= 1) {
        s += __shfl_xor_sync(0xffffffffu, s, o, 16);
        d += __shfl_xor_sync(0xffffffffu, d, o, 16);
    }
    if ((lane & 15) == 0) {
        int h = lane >> 4;
        g_als[gw * NHEAD + h] = s;
        g_ald[gw * NHEAD + h] = d;
    }
}

// Zero accumulators + init seg max/sum.
__global__ void k_init(int N) {
    int idx = blockIdx.x * blockDim.x + threadIdx.x;
    if (idx >= N * F) return;
    g_out[idx] = 0.f;
    if (idx < N * NHEAD) {
        g_segsum[idx] = 0.f;
        g_segmax[idx] = 0x007FFFFFu;  // fkey(-inf)
    }
}

// Per-edge segment max (ordered-uint atomicMax).
__global__ void k_edge_max(int EE) {
    int i = blockIdx.x * blockDim.x + threadIdx.x;
    if (i >= EE) return;
    int s = g_src[i], d = g_dst[i];
#pragma unroll
    for (int h = 0; h < NHEAD; h++) {
        float e = leaky(g_als[s * NHEAD + h] + g_ald[d * NHEAD + h]);
        atomicMax(&g_segmax[d * NHEAD + h], fkey(e));
    }
}

// Fused: ex = exp(e - m); denom += ex; out[d] += ex * h[s] (unnormalized).
// One warp per edge; lane covers 4 feats; lanes 0-15 head 0, 16-31 head 1.
__global__ void k_scatter(int EE) {
    int e = (blockIdx.x * blockDim.x + threadIdx.x) >> 5;
    if (e >= EE) return;
    int lane = threadIdx.x & 31;
    int s = g_src[e], d = g_dst[e];
    int head = lane >> 4;

    float ev = leaky(g_als[s * NHEAD + head] + g_ald[d * NHEAD + head]);
    float m = funkey(g_segmax[d * NHEAD + head]);
    float ex = __expf(ev - m);
    if ((lane & 15) == 0) atomicAdd(&g_segsum[d * NHEAD + head], ex);

    float4 hv = __ldg(((const float4*)g_h) + (size_t)s * 32 + lane);
    float* op = g_out + (size_t)d * F + lane * 4;
    asm volatile("red.global.add.v4.f32 [%0], {%1,%2,%3,%4};" ::"l"(op),
                 "f"(ex * hv.x), "f"(ex * hv.y), "f"(ex * hv.z), "f"(ex * hv.w)
                 : "memory");
}

// feat = leaky( [feat +] out/denom + bias )
__global__ void k_finalize(const float* __restrict__ bias, int residual, int N) {
    int idx = blockIdx.x * blockDim.x + threadIdx.x;
    if (idx >= N * F) return;
    int n = idx >> 7, c = idx & 127, head = c >> 6;
    float v = g_out[idx] / g_segsum[n * NHEAD + head] + __ldg(bias + c);
    if (residual) v += g_feat[idx];
    g_feat[idx] = leaky(v);
}

// logits[n] = dot(feat[n], lin_w) + lin_b
__global__ void k_lin(const float* __restrict__ lin_w, const float* __restrict__ lin_b,
                      float* __restrict__ out, int N) {
    int n = (blockIdx.x * blockDim.x + threadIdx.x) >> 5;
    if (n >= N) return;
    int lane = threadIdx.x & 31;
    float4 hv = ((const float4*)g_feat)[(size_t)n * 32 + lane];
    float4 wv = __ldg(((const float4*)lin_w) + lane);
    float s = hv.x * wv.x + hv.y * wv.y + hv.z * wv.z + hv.w * wv.w;
#pragma unroll
    for (int o = 16; o; o >>= 1) s += __shfl_xor_sync(0xffffffffu, s, o);
    if (lane == 0) out[n] = s + __ldg(lin_b);
}

// ---------------- host ----------------
extern "C" void kernel_launch(void* const* d_in, const int* in_sizes, int n_in,
                              void* d_out, int out_size) {
    const float* x = (const float*)d_in[0];
    const int* ei = (const int*)d_in[1];     // int32 (JAX demotes int64)
    const float* W1 = (const float*)d_in[2];
    const float* as1 = (const float*)d_in[3];
    const float* ad1 = (const float*)d_in[4];
    const float* b1 = (const float*)d_in[5];
    const float* W2 = (const float*)d_in[6];
    const float* as2 = (const float*)d_in[7];
    const float* ad2 = (const float*)d_in[8];
    const float* b2 = (const float*)d_in[9];
    const float* W3 = (const float*)d_in[10];
    const float* as3 = (const float*)d_in[11];
    const float* ad3 = (const float*)d_in[12];
    const float* b3 = (const float*)d_in[13];
    const float* lin_w = (const float*)d_in[14];
    const float* lin_b = (const float*)d_in[15];

    int N = in_sizes[0] / F;
    int E = in_sizes[1] / 2;
    int EE = E + N;

    static bool attr_done = false;
    const int GEMM_SMEM = (64 * F + F * F) * sizeof(float);  // 96 KB
    if (!attr_done) {
        cudaFuncSetAttribute(k_gemm128, cudaFuncAttributeMaxDynamicSharedMemorySize, GEMM_SMEM);
        attr_done = true;
    }

    float* feat_ptr = nullptr;
    cudaGetSymbolAddress((void**)&feat_ptr, g_feat);
    float* h_ptr = nullptr;
    cudaGetSymbolAddress((void**)&h_ptr, g_h);

    const int TB = 256;
    int gemm_blocks = (N + 63) / 64;
    int nf_blocks = (N * F + TB - 1) / TB;
    int warpN_blocks = (N * 32 + TB - 1) / TB;
    int edge_blocks = (EE + TB - 1) / TB;
    int scat_blocks = (int)(((size_t)EE * 32 + TB - 1) / TB);

    k_build_edges<<<edge_blocks, TB>>>(ei, E, N);

    // ---- layer 1 ----
    k_gemm128<<<gemm_blocks, TB, GEMM_SMEM>>>(x, W1, h_ptr, N);
    k_attn<<<warpN_blocks, TB>>>(as1, ad1, N);
    k_init<<<nf_blocks, TB>>>(N);
    k_edge_max<<<edge_blocks, TB>>>(EE);
    k_scatter<<<scat_blocks, TB>>>(EE);
    k_finalize<<<nf_blocks, TB>>>(b1, 0, N);

    // ---- layer 2 ----
    k_gemm128<<<gemm_blocks, TB, GEMM_SMEM>>>(feat_ptr, W2, h_ptr, N);
    k_attn<<<warpN_blocks, TB>>>(as2, ad2, N);
    k_init<<<nf_blocks, TB>>>(N);
    k_edge_max<<<edge_blocks, TB>>>(EE);
    k_scatter<<<scat_blocks, TB>>>(EE);
    k_finalize<<<nf_blocks, TB>>>(b2, 1, N);

    // ---- layer 3 ----
    k_gemm128<<<gemm_blocks, TB, GEMM_SMEM>>>(feat_ptr, W3, h_ptr, N);
    k_attn<<<warpN_blocks, TB>>>(as3, ad3, N);
    k_init<<<nf_blocks, TB>>>(N);
    k_edge_max<<<edge_blocks, TB>>>(EE);
    k_scatter<<<scat_blocks, TB>>>(EE);
    k_finalize<<<nf_blocks, TB>>>(b3, 1, N);

    // ---- output head ----
    k_lin<<<warpN_blocks, TB>>>(lin_w, lin_b, (float*)d_out, N);
}

// round 3
// speedup vs baseline: 2.0512x; 2.0512x over previous
#include <cuda_runtime.h>
#include <cstdint>

#define MAXN 50000
#define MAXE 800000
#define MAXEE (MAXN + MAXE)
#define F 128
#define NHEAD 2
#define NEG 0.2f
#define SCANB 256

// ---------------- scratch (device globals; no allocation) ----------------
__device__ float g_h[(size_t)MAXN * F];     // h = X @ W for current layer
__device__ float g_feat[(size_t)MAXN * F];  // layer activations
__device__ float g_als[MAXN * NHEAD];
__device__ float g_ald[MAXN * NHEAD];
__device__ int g_src[MAXEE];
__device__ int g_dst[MAXEE];
__device__ int g_cnt[MAXN];                 // per-dst degree
__device__ int g_incl[MAXN];                // block-local inclusive scan
__device__ int g_bsum[(MAXN + SCANB - 1) / SCANB];
__device__ int g_boff[(MAXN + SCANB - 1) / SCANB];
__device__ int g_rowptr[MAXN + 1];
__device__ int g_cur[MAXN];                 // fill cursor
__device__ int g_esrc[MAXEE];               // CSR: src ids grouped by dst

__device__ __forceinline__ float leaky(float x) { return x > 0.f ? x : NEG * x; }

// ---------------- graph build ----------------
__global__ void k_build_edges(const int* __restrict__ ei, int E, int N) {
    int i = blockIdx.x * blockDim.x + threadIdx.x;
    int EE = E + N;
    if (i >= EE) return;
    if (i < E) { g_src[i] = ei[i]; g_dst[i] = ei[E + i]; }
    else       { g_src[i] = i - E; g_dst[i] = i - E; }
    if (i < N) g_cnt[i] = 0;
}

__global__ void k_hist(int EE) {
    int i = blockIdx.x * blockDim.x + threadIdx.x;
    if (i < EE) atomicAdd(&g_cnt[g_dst[i]], 1);
}

// Per-block inclusive scan of counts (256/block) + block totals.
__global__ void k_scan1(int N) {
    __shared__ int sm[SCANB];
    int i = blockIdx.x * SCANB + threadIdx.x;
    int v = (i < N) ? g_cnt[i] : 0;
    sm[threadIdx.x] = v;
    __syncthreads();
#pragma unroll
    for (int o = 1; o < SCANB; o <<= 1) {
        int t = (threadIdx.x >= o) ? sm[threadIdx.x - o] : 0;
        __syncthreads();
        sm[threadIdx.x] += t;
        __syncthreads();
    }
    if (i < N) g_incl[i] = sm[threadIdx.x];
    if (threadIdx.x == SCANB - 1) g_bsum[blockIdx.x] = sm[SCANB - 1];
}

// Single-block exclusive scan of block sums (nb <= 256).
__global__ void k_scan2(int nb) {
    __shared__ int sm[SCANB];
    int v = (threadIdx.x < nb) ? g_bsum[threadIdx.x] : 0;
    sm[threadIdx.x] = v;
    __syncthreads();
#pragma unroll
    for (int o = 1; o < SCANB; o <<= 1) {
        int t = (threadIdx.x >= o) ? sm[threadIdx.x - o] : 0;
        __syncthreads();
        sm[threadIdx.x] += t;
        __syncthreads();
    }
    if (threadIdx.x < nb) g_boff[threadIdx.x] = sm[threadIdx.x] - v;  // exclusive
}

__global__ void k_scan3(int N, int EE) {
    int i = blockIdx.x * blockDim.x + threadIdx.x;
    if (i < N) {
        int excl = g_incl[i] - g_cnt[i] + g_boff[i / SCANB];
        g_rowptr[i] = excl;
        g_cur[i] = excl;
    }
    if (i == 0) g_rowptr[N] = EE;
}

__global__ void k_fill(int EE) {
    int i = blockIdx.x * blockDim.x + threadIdx.x;
    if (i >= EE) return;
    int pos = atomicAdd(&g_cur[g_dst[i]], 1);
    g_esrc[pos] = g_src[i];
}

// ---------------- dense ----------------
// H = A[N,128] @ W[128,128]. 256 thr / 64 rows per block, W staged in SMEM.
__global__ void k_gemm128(const float* __restrict__ A, const float* __restrict__ W,
                          float* __restrict__ Hout, int N) {
    extern __shared__ float sm[];
    float* Xs = sm;              // 64*128
    float* Ws = sm + 64 * F;     // 128*128
    int tid = threadIdx.x;
    int warp = tid >> 5, lane = tid & 31;
    int row0 = blockIdx.x * 64;

    const float4* W4 = (const float4*)W;
    float4* Ws4 = (float4*)Ws;
#pragma unroll
    for (int i = 0; i < 16; i++) Ws4[tid + i * 256] = W4[tid + i * 256];

    const float4* A4 = (const float4*)A;
    float4* Xs4 = (float4*)Xs;
#pragma unroll
    for (int i = 0; i < 8; i++) {
        int idx = tid + i * 256;
        int r = row0 + (idx >> 5);
        Xs4[idx] = (r < N) ? A4[(size_t)r * 32 + (idx & 31)]
                           : make_float4(0.f, 0.f, 0.f, 0.f);
    }
    __syncthreads();

    float4 acc[8];
#pragma unroll
    for (int i = 0; i < 8; i++) acc[i] = make_float4(0.f, 0.f, 0.f, 0.f);
    int rbase = warp * 8;

#pragma unroll 4
    for (int k = 0; k < F; k++) {
        float4 w = Ws4[k * 32 + lane];
#pragma unroll
        for (int r = 0; r < 8; r++) {
            float xv = Xs[(rbase + r) * F + k];
            acc[r].x += xv * w.x;
            acc[r].y += xv * w.y;
            acc[r].z += xv * w.z;
            acc[r].w += xv * w.w;
        }
    }
#pragma unroll
    for (int r = 0; r < 8; r++) {
        int rr = row0 + rbase + r;
        if (rr < N) ((float4*)Hout)[(size_t)rr * 32 + lane] = acc[r];
    }
}

// Per-node attention logits (one warp per node; 16 lanes per head).
__global__ void k_attn(const float* __restrict__ a_src, const float* __restrict__ a_dst, int N) {
    int gw = (blockIdx.x * blockDim.x + threadIdx.x) >> 5;
    if (gw >= N) return;
    int lane = threadIdx.x & 31;
    float4 hv = ((const float4*)g_h)[(size_t)gw * 32 + lane];
    float4 as = __ldg(((const float4*)a_src) + lane);
    float4 ad = __ldg(((const float4*)a_dst) + lane);
    float s = hv.x * as.x + hv.y * as.y + hv.z * as.z + hv.w * as.w;
    float d = hv.x * ad.x + hv.y * ad.y + hv.z * ad.z + hv.w * ad.w;
#pragma unroll
    for (int o = 8; o; o >>= 1) {
        s += __shfl_xor_sync(0xffffffffu, s, o, 16);
        d += __shfl_xor_sync(0xffffffffu, d, o, 16);
    }
    if ((lane & 15) == 0) {
        int h = lane >> 4;
        g_als[gw * NHEAD + h] = s;
        g_ald[gw * NHEAD + h] = d;
    }
}

// Fused CSR aggregation: softmax (no max-shift; logits are O(10), exp is safe
// in fp32 and the normalized ratio is identical) + weighted gather + bias +
// residual + LeakyReLU. One warp per dst node; lane covers 4 feats, head=lane/16.
__global__ void k_aggregate(const float* __restrict__ bias, int residual, int N) {
    int d = (blockIdx.x * blockDim.x + threadIdx.x) >> 5;
    if (d >= N) return;
    int lane = threadIdx.x & 31;
    int head = lane >> 4;

    float ald = g_ald[d * NHEAD + head];
    int beg = g_rowptr[d], end = g_rowptr[d + 1];

    float4 acc = make_float4(0.f, 0.f, 0.f, 0.f);
    float sum = 0.f;
    const float4* H4 = (const float4*)g_h;

    int j = beg;
    for (; j + 4 <= end; j += 4) {
        int s0 = g_esrc[j], s1 = g_esrc[j + 1], s2 = g_esrc[j + 2], s3 = g_esrc[j + 3];
        float e0 = __expf(leaky(g_als[s0 * NHEAD + head] + ald));
        float e1 = __expf(leaky(g_als[s1 * NHEAD + head] + ald));
        float e2 = __expf(leaky(g_als[s2 * NHEAD + head] + ald));
        float e3 = __expf(leaky(g_als[s3 * NHEAD + head] + ald));
        float4 h0 = __ldg(H4 + (size_t)s0 * 32 + lane);
        float4 h1 = __ldg(H4 + (size_t)s1 * 32 + lane);
        float4 h2 = __ldg(H4 + (size_t)s2 * 32 + lane);
        float4 h3 = __ldg(H4 + (size_t)s3 * 32 + lane);
        sum += (e0 + e1) + (e2 + e3);
        acc.x += e0 * h0.x + e1 * h1.x + e2 * h2.x + e3 * h3.x;
        acc.y += e0 * h0.y + e1 * h1.y + e2 * h2.y + e3 * h3.y;
        acc.z += e0 * h0.z + e1 * h1.z + e2 * h2.z + e3 * h3.z;
        acc.w += e0 * h0.w + e1 * h1.w + e2 * h2.w + e3 * h3.w;
    }
    for (; j < end; j++) {
        int s = g_esrc[j];
        float ex = __expf(leaky(g_als[s * NHEAD + head] + ald));
        float4 hv = __ldg(H4 + (size_t)s * 32 + lane);
        sum += ex;
        acc.x += ex * hv.x; acc.y += ex * hv.y;
        acc.z += ex * hv.z; acc.w += ex * hv.w;
    }

    float inv = 1.f / sum;  // every node has a self loop -> sum > 0
    float4 b = __ldg(((const float4*)bias) + lane);
    float4 v;
    v.x = acc.x * inv + b.x; v.y = acc.y * inv + b.y;
    v.z = acc.z * inv + b.z; v.w = acc.w * inv + b.w;
    float4* FP = (float4*)g_feat + (size_t)d * 32 + lane;
    if (residual) {
        float4 f = *FP;
        v.x += f.x; v.y += f.y; v.z += f.z; v.w += f.w;
    }
    v.x = leaky(v.x); v.y = leaky(v.y); v.z = leaky(v.z); v.w = leaky(v.w);
    *FP = v;
}

// logits[n] = dot(feat[n], lin_w) + lin_b
__global__ void k_lin(const float* __restrict__ lin_w, const float* __restrict__ lin_b,
                      float* __restrict__ out, int N) {
    int n = (blockIdx.x * blockDim.x + threadIdx.x) >> 5;
    if (n >= N) return;
    int lane = threadIdx.x & 31;
    float4 hv = ((const float4*)g_feat)[(size_t)n * 32 + lane];
    float4 wv = __ldg(((const float4*)lin_w) + lane);
    float s = hv.x * wv.x + hv.y * wv.y + hv.z * wv.z + hv.w * wv.w;
#pragma unroll
    for (int o = 16; o; o >>= 1) s += __shfl_xor_sync(0xffffffffu, s, o);
    if (lane == 0) out[n] = s + __ldg(lin_b);
}

// ---------------- host ----------------
extern "C" void kernel_launch(void* const* d_in, const int* in_sizes, int n_in,
                              void* d_out, int out_size) {
    const float* x = (const float*)d_in[0];
    const int* ei = (const int*)d_in[1];
    const float* W1 = (const float*)d_in[2];
    const float* as1 = (const float*)d_in[3];
    const float* ad1 = (const float*)d_in[4];
    const float* b1 = (const float*)d_in[5];
    const float* W2 = (const float*)d_in[6];
    const float* as2 = (const float*)d_in[7];
    const float* ad2 = (const float*)d_in[8];
    const float* b2 = (const float*)d_in[9];
    const float* W3 = (const float*)d_in[10];
    const float* as3 = (const float*)d_in[11];
    const float* ad3 = (const float*)d_in[12];
    const float* b3 = (const float*)d_in[13];
    const float* lin_w = (const float*)d_in[14];
    const float* lin_b = (const float*)d_in[15];

    int N = in_sizes[0] / F;
    int E = in_sizes[1] / 2;
    int EE = E + N;
    int nb = (N + SCANB - 1) / SCANB;

    static bool attr_done = false;
    const int GEMM_SMEM = (64 * F + F * F) * sizeof(float);  // 96 KB
    if (!attr_done) {
        cudaFuncSetAttribute(k_gemm128, cudaFuncAttributeMaxDynamicSharedMemorySize, GEMM_SMEM);
        attr_done = true;
    }

    float* feat_ptr = nullptr;
    cudaGetSymbolAddress((void**)&feat_ptr, g_feat);
    float* h_ptr = nullptr;
    cudaGetSymbolAddress((void**)&h_ptr, g_h);

    const int TB = 256;
    int gemm_blocks = (N + 63) / 64;
    int warpN_blocks = (N * 32 + TB - 1) / TB;
    int edge_blocks = (EE + TB - 1) / TB;
    int node_blocks = (N + TB - 1) / TB;

    // ---- CSR build (once; shared by all 3 layers) ----
    k_build_edges<<<edge_blocks, TB>>>(ei, E, N);
    k_hist<<<edge_blocks, TB>>>(EE);
    k_scan1<<<nb, SCANB>>>(N);
    k_scan2<<<1, SCANB>>>(nb);
    k_scan3<<<node_blocks, TB>>>(N, EE);
    k_fill<<<edge_blocks, TB>>>(EE);

    // ---- layer 1 ----
    k_gemm128<<<gemm_blocks, TB, GEMM_SMEM>>>(x, W1, h_ptr, N);
    k_attn<<<warpN_blocks, TB>>>(as1, ad1, N);
    k_aggregate<<<warpN_blocks, TB>>>(b1, 0, N);

    // ---- layer 2 ----
    k_gemm128<<<gemm_blocks, TB, GEMM_SMEM>>>(feat_ptr, W2, h_ptr, N);
    k_attn<<<warpN_blocks, TB>>>(as2, ad2, N);
    k_aggregate<<<warpN_blocks, TB>>>(b2, 1, N);

    // ---- layer 3 ----
    k_gemm128<<<gemm_blocks, TB, GEMM_SMEM>>>(feat_ptr, W3, h_ptr, N);
    k_attn<<<warpN_blocks, TB>>>(as3, ad3, N);
    k_aggregate<<<warpN_blocks, TB>>>(b3, 1, N);

    // ---- output head ----
    k_lin<<<warpN_blocks, TB>>>(lin_w, lin_b, (float*)d_out, N);
}

// round 5
// speedup vs baseline: 2.7749x; 1.3528x over previous
#include <cuda_runtime.h>
#include <cuda_bf16.h>
#include <cstdint>

#define MAXN 50000
#define MAXE 800000
#define MAXEE (MAXN + MAXE)
#define F 128
#define NHEAD 2
#define NEG 0.2f
#define SCANB 256
#define TM 128

// ---------------- scratch (device globals; no allocation) ----------------
__device__ float g_h[(size_t)MAXN * F];
__device__ float g_feat[(size_t)MAXN * F];
__device__ float g_als[MAXN * NHEAD];
__device__ float g_ald[MAXN * NHEAD];
__device__ int g_src[MAXEE];
__device__ int g_dst[MAXEE];
__device__ int g_cnt[MAXN];
__device__ int g_incl[MAXN];
__device__ int g_bsum[(MAXN + SCANB - 1) / SCANB];
__device__ int g_boff[(MAXN + SCANB - 1) / SCANB];
__device__ int g_rowptr[MAXN + 1];
__device__ int g_cur[MAXN];
__device__ int g_esrc[MAXEE];
__device__ __nv_bfloat16 g_wth[3][F * F];   // W^T hi, [n][k]
__device__ __nv_bfloat16 g_wtl[3][F * F];   // W^T lo, [n][k]

__device__ __forceinline__ float leaky(float x) { return x > 0.f ? x : NEG * x; }

__device__ __forceinline__ uint32_t smem_u32(const void* p) {
    uint32_t a;
    asm("{ .reg .u64 t; cvta.to.shared.u64 t, %1; cvt.u32.u64 %0, t; }" : "=r"(a) : "l"(p));
    return a;
}

// ---------------- graph build ----------------
__global__ void k_build_edges(const int* __restrict__ ei, int E, int N) {
    int i = blockIdx.x * blockDim.x + threadIdx.x;
    int EE = E + N;
    if (i >= EE) return;
    if (i < E) { g_src[i] = ei[i]; g_dst[i] = ei[E + i]; }
    else       { g_src[i] = i - E; g_dst[i] = i - E; }
    if (i < N) g_cnt[i] = 0;
}
__global__ void k_hist(int EE) {
    int i = blockIdx.x * blockDim.x + threadIdx.x;
    if (i < EE) atomicAdd(&g_cnt[g_dst[i]], 1);
}
__global__ void k_scan1(int N) {
    __shared__ int sm[SCANB];
    int i = blockIdx.x * SCANB + threadIdx.x;
    int v = (i < N) ? g_cnt[i] : 0;
    sm[threadIdx.x] = v;
    __syncthreads();
#pragma unroll
    for (int o = 1; o < SCANB; o <<= 1) {
        int t = (threadIdx.x >= o) ? sm[threadIdx.x - o] : 0;
        __syncthreads();
        sm[threadIdx.x] += t;
        __syncthreads();
    }
    if (i < N) g_incl[i] = sm[threadIdx.x];
    if (threadIdx.x == SCANB - 1) g_bsum[blockIdx.x] = sm[SCANB - 1];
}
__global__ void k_scan2(int nb) {
    __shared__ int sm[SCANB];
    int v = (threadIdx.x < nb) ? g_bsum[threadIdx.x] : 0;
    sm[threadIdx.x] = v;
    __syncthreads();
#pragma unroll
    for (int o = 1; o < SCANB; o <<= 1) {
        int t = (threadIdx.x >= o) ? sm[threadIdx.x - o] : 0;
        __syncthreads();
        sm[threadIdx.x] += t;
        __syncthreads();
    }
    if (threadIdx.x < nb) g_boff[threadIdx.x] = sm[threadIdx.x] - v;
}
__global__ void k_scan3(int N, int EE) {
    int i = blockIdx.x * blockDim.x + threadIdx.x;
    if (i < N) {
        int excl = g_incl[i] - g_cnt[i] + g_boff[i / SCANB];
        g_rowptr[i] = excl;
        g_cur[i] = excl;
    }
    if (i == 0) g_rowptr[N] = EE;
}
__global__ void k_fill(int EE) {
    int i = blockIdx.x * blockDim.x + threadIdx.x;
    if (i >= EE) return;
    int pos = atomicAdd(&g_cur[g_dst[i]], 1);
    g_esrc[pos] = g_src[i];
}

// ---------------- W prep: transpose + hi/lo bf16 split ----------------
__global__ void k_prep_w(const float* __restrict__ W, __nv_bfloat16* __restrict__ wth,
                         __nv_bfloat16* __restrict__ wtl) {
    int i = blockIdx.x * blockDim.x + threadIdx.x;
    if (i >= F * F) return;
    int k = i / F, n = i % F;
    float v = W[i];
    __nv_bfloat16 h = __float2bfloat16_rn(v);
    float r = v - __bfloat162float(h);
    wth[n * F + k] = h;
    wtl[n * F + k] = __float2bfloat16_rn(r);
}

// ---------------- mma.sync GEMM + fused attention logits ----------------
// SMEM: a_src[128]f, a_dst[128]f, then 4 bf16 tiles 128x136 (padded stride).
#define TSTRIDE 136                       // bf16 elements per padded row
#define TROWB (TSTRIDE * 2)               // 272 bytes
#define TILE_BYTES (128 * TROWB)          // 34816
#define OFF_AS 0
#define OFF_AD 512
#define OFF_XHI 1024
#define OFF_XLO (OFF_XHI + TILE_BYTES)
#define OFF_WHI (OFF_XLO + TILE_BYTES)
#define OFF_WLO (OFF_WHI + TILE_BYTES)
#define GEMM_SMEM_TOTAL (OFF_WLO + TILE_BYTES)

__device__ __forceinline__ void ldsm4(uint32_t addr, uint32_t& r0, uint32_t& r1,
                                      uint32_t& r2, uint32_t& r3) {
    asm volatile("ldmatrix.sync.aligned.m8n8.x4.shared.b16 {%0,%1,%2,%3}, [%4];"
                 : "=r"(r0), "=r"(r1), "=r"(r2), "=r"(r3) : "r"(addr));
}
__device__ __forceinline__ void mma16816(float* c, const uint32_t* a, uint32_t b0, uint32_t b1) {
    asm volatile(
        "mma.sync.aligned.m16n8k16.row.col.f32.bf16.bf16.f32 "
        "{%0,%1,%2,%3}, {%4,%5,%6,%7}, {%8,%9}, {%0,%1,%2,%3};"
        : "+f"(c[0]), "+f"(c[1]), "+f"(c[2]), "+f"(c[3])
        : "r"(a[0]), "r"(a[1]), "r"(a[2]), "r"(a[3]), "r"(b0), "r"(b1));
}
__device__ __forceinline__ uint32_t pack_bf16x2(float a, float b) {
    __nv_bfloat16 ha = __float2bfloat16_rn(a), hb = __float2bfloat16_rn(b);
    return (uint32_t)__bfloat16_as_ushort(ha) | ((uint32_t)__bfloat16_as_ushort(hb) << 16);
}

__global__ void __launch_bounds__(256, 1)
k_gemm_tc(const float* __restrict__ A, const __nv_bfloat16* __restrict__ wth,
          const __nv_bfloat16* __restrict__ wtl, const float* __restrict__ a_src,
          const float* __restrict__ a_dst, float* __restrict__ Hout, int N) {
    extern __shared__ char smem[];
    uint32_t sb = smem_u32(smem);
    int tid = threadIdx.x;
    int wid = tid >> 5, lane = tid & 31;
    int row0 = blockIdx.x * TM;

    if (tid < F) {
        *(float*)(smem + OFF_AS + tid * 4) = __ldg(a_src + tid);
        *(float*)(smem + OFF_AD + tid * 4) = __ldg(a_dst + tid);
    }

    // X tile -> bf16 hi/lo, padded-stride SMEM
    const float4* A4 = (const float4*)A;
#pragma unroll
    for (int it = 0; it < 16; it++) {
        int i = tid + it * 256;                 // float4 index in 128x32-float4 tile
        int r = i >> 5, c4 = (i & 31) << 2;
        int gr = row0 + r;
        float4 v = (gr < N) ? A4[(size_t)gr * 32 + (i & 31)] : make_float4(0.f, 0.f, 0.f, 0.f);
        uint2 hi, lo;
        hi.x = pack_bf16x2(v.x, v.y);
        hi.y = pack_bf16x2(v.z, v.w);
        float rx = v.x - __bfloat162float(__float2bfloat16_rn(v.x));
        float ry = v.y - __bfloat162float(__float2bfloat16_rn(v.y));
        float rz = v.z - __bfloat162float(__float2bfloat16_rn(v.z));
        float rw = v.w - __bfloat162float(__float2bfloat16_rn(v.w));
        lo.x = pack_bf16x2(rx, ry);
        lo.y = pack_bf16x2(rz, rw);
        uint32_t off = (uint32_t)(r * TROWB + c4 * 2);
        *(uint2*)(smem + OFF_XHI + off) = hi;
        *(uint2*)(smem + OFF_XLO + off) = lo;
    }
    // W^T hi/lo -> padded-stride SMEM
    const uint2* WH2 = (const uint2*)wth;
    const uint2* WL2 = (const uint2*)wtl;
#pragma unroll
    for (int it = 0; it < 16; it++) {
        int i = tid + it * 256;                 // uint2 (4 bf16) index
        int r = i >> 5, c4 = (i & 31) << 2;
        uint32_t off = (uint32_t)(r * TROWB + c4 * 2);
        *(uint2*)(smem + OFF_WHI + off) = WH2[i];
        *(uint2*)(smem + OFF_WLO + off) = WL2[i];
    }
    __syncthreads();

    int warp_m = wid & 3;        // 4 row groups of 32
    int warp_n = wid >> 2;       // 2 col groups of 64 (== head)
    int m0 = warp_m * 32;
    int n0 = warp_n * 64;

    float acc[2][8][4];
#pragma unroll
    for (int mt = 0; mt < 2; mt++)
#pragma unroll
        for (int nt = 0; nt < 8; nt++)
#pragma unroll
            for (int q = 0; q < 4; q++) acc[mt][nt][q] = 0.f;

    // A-frag ldmatrix address pieces (row-major [m][k])
    int a_row_in = (lane & 7) + ((lane >> 3) & 1) * 8;     // row within m16
    int a_koff = (lane >> 4) * 16;                          // byte offset along k
    // B-frag ldmatrix address pieces ([n][k], no trans)
    int b_row_in = (lane & 7) + ((lane >> 4) & 1) * 8;     // row within n16 pair
    int b_koff = ((lane >> 3) & 1) * 16;

#pragma unroll
    for (int t = 0; t < 3; t++) {
        uint32_t abase = sb + ((t == 2) ? OFF_XLO : OFF_XHI);
        uint32_t bbase = sb + ((t == 1) ? OFF_WLO : OFF_WHI);
#pragma unroll
        for (int ks = 0; ks < 8; ks++) {
            int kb = ks * 32;  // byte offset of k0 (16 bf16)
            uint32_t afr[2][4];
#pragma unroll
            for (int mt = 0; mt < 2; mt++) {
                uint32_t ad = abase + (uint32_t)((m0 + mt * 16 + a_row_in) * TROWB + kb + a_koff);
                ldsm4(ad, afr[mt][0], afr[mt][1], afr[mt][2], afr[mt][3]);
            }
            uint32_t bfr[4][4];
#pragma unroll
            for (int pt = 0; pt < 4; pt++) {
                uint32_t bd = bbase + (uint32_t)((n0 + pt * 16 + b_row_in) * TROWB + kb + b_koff);
                ldsm4(bd, bfr[pt][0], bfr[pt][1], bfr[pt][2], bfr[pt][3]);
            }
#pragma unroll
            for (int mt = 0; mt < 2; mt++)
#pragma unroll
                for (int nt = 0; nt < 8; nt++)
                    mma16816(acc[mt][nt], afr[mt], bfr[nt >> 1][(nt & 1) * 2],
                             bfr[nt >> 1][(nt & 1) * 2 + 1]);
        }
    }

    // epilogue: store H + fused attention-logit dots (this warp's head only)
    const float* sAS = (const float*)(smem + OFF_AS);
    const float* sAD = (const float*)(smem + OFF_AD);
    float ss[2][2] = {{0.f, 0.f}, {0.f, 0.f}};   // [mt][rowhalf] src dots
    float dd[2][2] = {{0.f, 0.f}, {0.f, 0.f}};
#pragma unroll
    for (int nt = 0; nt < 8; nt++) {
        int col = n0 + nt * 8 + ((lane & 3) << 1);
        float as0 = sAS[col], as1 = sAS[col + 1];
        float ad0 = sAD[col], ad1 = sAD[col + 1];
#pragma unroll
        for (int mt = 0; mt < 2; mt++) {
            float c0 = acc[mt][nt][0], c1 = acc[mt][nt][1];
            float c2 = acc[mt][nt][2], c3 = acc[mt][nt][3];
            int r0 = row0 + m0 + mt * 16 + (lane >> 2);
            if (r0 < N) *(float2*)(Hout + (size_t)r0 * F + col) = make_float2(c0, c1);
            if (r0 + 8 < N) *(float2*)(Hout + (size_t)(r0 + 8) * F + col) = make_float2(c2, c3);
            ss[mt][0] += c0 * as0 + c1 * as1;
            ss[mt][1] += c2 * as0 + c3 * as1;
            dd[mt][0] += c0 * ad0 + c1 * ad1;
            dd[mt][1] += c2 * ad0 + c3 * ad1;
        }
    }
#pragma unroll
    for (int mt = 0; mt < 2; mt++)
#pragma unroll
        for (int rh = 0; rh < 2; rh++) {
            ss[mt][rh] += __shfl_xor_sync(0xffffffffu, ss[mt][rh], 1);
            ss[mt][rh] += __shfl_xor_sync(0xffffffffu, ss[mt][rh], 2);
            dd[mt][rh] += __shfl_xor_sync(0xffffffffu, dd[mt][rh], 1);
            dd[mt][rh] += __shfl_xor_sync(0xffffffffu, dd[mt][rh], 2);
        }
    if ((lane & 3) == 0) {
#pragma unroll
        for (int mt = 0; mt < 2; mt++)
#pragma unroll
            for (int rh = 0; rh < 2; rh++) {
                int m = row0 + m0 + mt * 16 + rh * 8 + (lane >> 2);
                if (m < N) {
                    g_als[m * NHEAD + warp_n] = ss[mt][rh];
                    g_ald[m * NHEAD + warp_n] = dd[mt][rh];
                }
            }
    }
}

// ---------------- fused CSR aggregation ----------------
__global__ void k_aggregate(const float* __restrict__ bias, int residual, int N) {
    int d = (blockIdx.x * blockDim.x + threadIdx.x) >> 5;
    if (d >= N) return;
    int lane = threadIdx.x & 31;
    int head = lane >> 4;

    float ald = g_ald[d * NHEAD + head];
    int beg = g_rowptr[d], end = g_rowptr[d + 1];

    float4 acc = make_float4(0.f, 0.f, 0.f, 0.f);
    float sum = 0.f;
    const float4* H4 = (const float4*)g_h;

    int j = beg;
    for (; j + 4 <= end; j += 4) {
        int s0 = g_esrc[j], s1 = g_esrc[j + 1], s2 = g_esrc[j + 2], s3 = g_esrc[j + 3];
        float e0 = __expf(leaky(g_als[s0 * NHEAD + head] + ald));
        float e1 = __expf(leaky(g_als[s1 * NHEAD + head] + ald));
        float e2 = __expf(leaky(g_als[s2 * NHEAD + head] + ald));
        float e3 = __expf(leaky(g_als[s3 * NHEAD + head] + ald));
        float4 h0 = __ldg(H4 + (size_t)s0 * 32 + lane);
        float4 h1 = __ldg(H4 + (size_t)s1 * 32 + lane);
        float4 h2 = __ldg(H4 + (size_t)s2 * 32 + lane);
        float4 h3 = __ldg(H4 + (size_t)s3 * 32 + lane);
        sum += (e0 + e1) + (e2 + e3);
        acc.x += e0 * h0.x + e1 * h1.x + e2 * h2.x + e3 * h3.x;
        acc.y += e0 * h0.y + e1 * h1.y + e2 * h2.y + e3 * h3.y;
        acc.z += e0 * h0.z + e1 * h1.z + e2 * h2.z + e3 * h3.z;
        acc.w += e0 * h0.w + e1 * h1.w + e2 * h2.w + e3 * h3.w;
    }
    for (; j < end; j++) {
        int s = g_esrc[j];
        float ex = __expf(leaky(g_als[s * NHEAD + head] + ald));
        float4 hv = __ldg(H4 + (size_t)s * 32 + lane);
        sum += ex;
        acc.x += ex * hv.x; acc.y += ex * hv.y;
        acc.z += ex * hv.z; acc.w += ex * hv.w;
    }

    float inv = 1.f / sum;
    float4 b = __ldg(((const float4*)bias) + lane);
    float4 v;
    v.x = acc.x * inv + b.x; v.y = acc.y * inv + b.y;
    v.z = acc.z * inv + b.z; v.w = acc.w * inv + b.w;
    float4* FP = (float4*)g_feat + (size_t)d * 32 + lane;
    if (residual) {
        float4 f = *FP;
        v.x += f.x; v.y += f.y; v.z += f.z; v.w += f.w;
    }
    v.x = leaky(v.x); v.y = leaky(v.y); v.z = leaky(v.z); v.w = leaky(v.w);
    *FP = v;
}

// logits[n] = dot(feat[n], lin_w) + lin_b
__global__ void k_lin(const float* __restrict__ lin_w, const float* __restrict__ lin_b,
                      float* __restrict__ out, int N) {
    int n = (blockIdx.x * blockDim.x + threadIdx.x) >> 5;
    if (n >= N) return;
    int lane = threadIdx.x & 31;
    float4 hv = ((const float4*)g_feat)[(size_t)n * 32 + lane];
    float4 wv = __ldg(((const float4*)lin_w) + lane);
    float s = hv.x * wv.x + hv.y * wv.y + hv.z * wv.z + hv.w * wv.w;
#pragma unroll
    for (int o = 16; o; o >>= 1) s += __shfl_xor_sync(0xffffffffu, s, o);
    if (lane == 0) out[n] = s + __ldg(lin_b);
}

// ---------------- host ----------------
extern "C" void kernel_launch(void* const* d_in, const int* in_sizes, int n_in,
                              void* d_out, int out_size) {
    const float* x = (const float*)d_in[0];
    const int* ei = (const int*)d_in[1];
    const float* W[3] = {(const float*)d_in[2], (const float*)d_in[6], (const float*)d_in[10]};
    const float* as[3] = {(const float*)d_in[3], (const float*)d_in[7], (const float*)d_in[11]};
    const float* ad[3] = {(const float*)d_in[4], (const float*)d_in[8], (const float*)d_in[12]};
    const float* bs[3] = {(const float*)d_in[5], (const float*)d_in[9], (const float*)d_in[13]};
    const float* lin_w = (const float*)d_in[14];
    const float* lin_b = (const float*)d_in[15];

    int N = in_sizes[0] / F;
    int E = in_sizes[1] / 2;
    int EE = E + N;
    int nb = (N + SCANB - 1) / SCANB;

    static bool attr_done = false;
    if (!attr_done) {
        cudaFuncSetAttribute(k_gemm_tc, cudaFuncAttributeMaxDynamicSharedMemorySize,
                             GEMM_SMEM_TOTAL);
        attr_done = true;
    }

    float* feat_ptr = nullptr;
    cudaGetSymbolAddress((void**)&feat_ptr, g_feat);
    float* h_ptr = nullptr;
    cudaGetSymbolAddress((void**)&h_ptr, g_h);
    __nv_bfloat16* wth_ptr = nullptr;
    cudaGetSymbolAddress((void**)&wth_ptr, g_wth);
    __nv_bfloat16* wtl_ptr = nullptr;
    cudaGetSymbolAddress((void**)&wtl_ptr, g_wtl);

    const int TB = 256;
    int gemm_blocks = (N + TM - 1) / TM;
    int warpN_blocks = (N * 32 + TB - 1) / TB;
    int edge_blocks = (EE + TB - 1) / TB;
    int node_blocks = (N + TB - 1) / TB;
    int prep_blocks = (F * F + TB - 1) / TB;

    // ---- CSR build + W prep ----
    k_build_edges<<<edge_blocks, TB>>>(ei, E, N);
    k_hist<<<edge_blocks, TB>>>(EE);
    k_scan1<<<nb, SCANB>>>(N);
    k_scan2<<<1, SCANB>>>(nb);
    k_scan3<<<node_blocks, TB>>>(N, EE);
    k_fill<<<edge_blocks, TB>>>(EE);
    for (int l = 0; l < 3; l++)
        k_prep_w<<<prep_blocks, TB>>>(W[l], wth_ptr + (size_t)l * F * F,
                                      wtl_ptr + (size_t)l * F * F);

    // ---- 3 GAT layers ----
    for (int l = 0; l < 3; l++) {
        const float* in = (l == 0) ? x : feat_ptr;
        k_gemm_tc<<<gemm_blocks, 256, GEMM_SMEM_TOTAL>>>(
            in, wth_ptr + (size_t)l * F * F, wtl_ptr + (size_t)l * F * F,
            as[l], ad[l], h_ptr, N);
        k_aggregate<<<warpN_blocks, TB>>>(bs[l], l > 0, N);
    }

    // ---- output head ----
    k_lin<<<warpN_blocks, TB>>>(lin_w, lin_b, (float*)d_out, N);
}

// round 6
// speedup vs baseline: 3.0665x; 1.1051x over previous
#include <cuda_runtime.h>
#include <cuda_bf16.h>
#include <cuda_fp16.h>
#include <cstdint>

#define MAXN 50000
#define MAXE 800000
#define MAXEE (MAXN + MAXE)
#define F 128
#define NHEAD 2
#define NEG 0.2f
#define SCANB 256
#define TM 128

// ---------------- scratch (device globals; no allocation) ----------------
__device__ __half g_hh[(size_t)MAXN * F];   // h in fp16 (gather path)
__device__ float g_feat[(size_t)MAXN * F];
__device__ float g_als[MAXN * NHEAD];
__device__ float g_ald[MAXN * NHEAD];
__device__ int g_src[MAXEE];
__device__ int g_dst[MAXEE];
__device__ int g_cnt[MAXN];
__device__ int g_incl[MAXN];
__device__ int g_bsum[(MAXN + SCANB - 1) / SCANB];
__device__ int g_rowptr[MAXN + 1];
__device__ int g_cur[MAXN];
__device__ int g_esrc[MAXEE];
__device__ __nv_bfloat16 g_wth[3][F * F];   // W^T hi, [n][k]
__device__ __nv_bfloat16 g_wtl[3][F * F];   // W^T lo, [n][k]

__device__ __forceinline__ float leaky(float x) { return x > 0.f ? x : NEG * x; }

__device__ __forceinline__ uint32_t smem_u32(const void* p) {
    uint32_t a;
    asm("{ .reg .u64 t; cvta.to.shared.u64 t, %1; cvt.u32.u64 %0, t; }" : "=r"(a) : "l"(p));
    return a;
}

// ---------------- graph build ----------------
// build src/dst (+self loops) and histogram in one pass (g_cnt pre-zeroed).
__global__ void k_build_hist(const int* __restrict__ ei, int E, int N) {
    int i = blockIdx.x * blockDim.x + threadIdx.x;
    int EE = E + N;
    if (i >= EE) return;
    int s, d;
    if (i < E) { s = ei[i]; d = ei[E + i]; }
    else       { s = i - E; d = i - E; }
    g_src[i] = s;
    g_dst[i] = d;
    atomicAdd(&g_cnt[d], 1);
}
__global__ void k_scan1(int N) {
    __shared__ int sm[SCANB];
    int i = blockIdx.x * SCANB + threadIdx.x;
    int v = (i < N) ? g_cnt[i] : 0;
    sm[threadIdx.x] = v;
    __syncthreads();
#pragma unroll
    for (int o = 1; o < SCANB; o <<= 1) {
        int t = (threadIdx.x >= o) ? sm[threadIdx.x - o] : 0;
        __syncthreads();
        sm[threadIdx.x] += t;
        __syncthreads();
    }
    if (i < N) g_incl[i] = sm[threadIdx.x];
    if (threadIdx.x == SCANB - 1) g_bsum[blockIdx.x] = sm[SCANB - 1];
}
// each block redundantly scans the <=256 block sums, then finishes rowptr/cur.
__global__ void k_scan23(int N, int EE, int nb) {
    __shared__ int sm[SCANB];
    int v = (threadIdx.x < nb) ? g_bsum[threadIdx.x] : 0;
    sm[threadIdx.x] = v;
    __syncthreads();
#pragma unroll
    for (int o = 1; o < SCANB; o <<= 1) {
        int t = (threadIdx.x >= o) ? sm[threadIdx.x - o] : 0;
        __syncthreads();
        sm[threadIdx.x] += t;
        __syncthreads();
    }
    int bid = blockIdx.x;
    int boff = sm[bid] - g_bsum[bid];   // exclusive prefix of this block
    int i = bid * SCANB + threadIdx.x;
    if (i < N) {
        int excl = g_incl[i] - g_cnt[i] + boff;
        g_rowptr[i] = excl;
        g_cur[i] = excl;
    }
    if (i == 0) g_rowptr[N] = EE;
}
__global__ void k_fill(int EE) {
    int i = blockIdx.x * blockDim.x + threadIdx.x;
    if (i >= EE) return;
    int pos = atomicAdd(&g_cur[g_dst[i]], 1);
    g_esrc[pos] = g_src[i];
}

// ---------------- W prep: transpose + hi/lo bf16 split, all 3 layers ----------------
__global__ void k_prep_w3(const float* __restrict__ W0, const float* __restrict__ W1,
                          const float* __restrict__ W2) {
    int i = blockIdx.x * blockDim.x + threadIdx.x;
    if (i >= 3 * F * F) return;
    int l = i / (F * F), j = i % (F * F);
    const float* W = (l == 0) ? W0 : ((l == 1) ? W1 : W2);
    int k = j / F, n = j % F;
    float v = W[j];
    __nv_bfloat16 h = __float2bfloat16_rn(v);
    float r = v - __bfloat162float(h);
    g_wth[l][n * F + k] = h;
    g_wtl[l][n * F + k] = __float2bfloat16_rn(r);
}

// ---------------- mma.sync GEMM + fused attention logits ----------------
#define TSTRIDE 136
#define TROWB (TSTRIDE * 2)
#define TILE_BYTES (128 * TROWB)
#define OFF_AS 0
#define OFF_AD 512
#define OFF_XHI 1024
#define OFF_XLO (OFF_XHI + TILE_BYTES)
#define OFF_WHI (OFF_XLO + TILE_BYTES)
#define OFF_WLO (OFF_WHI + TILE_BYTES)
#define GEMM_SMEM_TOTAL (OFF_WLO + TILE_BYTES)

__device__ __forceinline__ void ldsm4(uint32_t addr, uint32_t& r0, uint32_t& r1,
                                      uint32_t& r2, uint32_t& r3) {
    asm volatile("ldmatrix.sync.aligned.m8n8.x4.shared.b16 {%0,%1,%2,%3}, [%4];"
                 : "=r"(r0), "=r"(r1), "=r"(r2), "=r"(r3) : "r"(addr));
}
__device__ __forceinline__ void mma16816(float* c, const uint32_t* a, uint32_t b0, uint32_t b1) {
    asm volatile(
        "mma.sync.aligned.m16n8k16.row.col.f32.bf16.bf16.f32 "
        "{%0,%1,%2,%3}, {%4,%5,%6,%7}, {%8,%9}, {%0,%1,%2,%3};"
        : "+f"(c[0]), "+f"(c[1]), "+f"(c[2]), "+f"(c[3])
        : "r"(a[0]), "r"(a[1]), "r"(a[2]), "r"(a[3]), "r"(b0), "r"(b1));
}
__device__ __forceinline__ uint32_t pack_bf16x2(float a, float b) {
    __nv_bfloat16 ha = __float2bfloat16_rn(a), hb = __float2bfloat16_rn(b);
    return (uint32_t)__bfloat16_as_ushort(ha) | ((uint32_t)__bfloat16_as_ushort(hb) << 16);
}

__global__ void __launch_bounds__(256, 1)
k_gemm_tc(const float* __restrict__ A, const __nv_bfloat16* __restrict__ wth,
          const __nv_bfloat16* __restrict__ wtl, const float* __restrict__ a_src,
          const float* __restrict__ a_dst, int N) {
    extern __shared__ char smem[];
    uint32_t sb = smem_u32(smem);
    int tid = threadIdx.x;
    int wid = tid >> 5, lane = tid & 31;
    int row0 = blockIdx.x * TM;

    if (tid < F) {
        *(float*)(smem + OFF_AS + tid * 4) = __ldg(a_src + tid);
        *(float*)(smem + OFF_AD + tid * 4) = __ldg(a_dst + tid);
    }

    const float4* A4 = (const float4*)A;
#pragma unroll
    for (int it = 0; it < 16; it++) {
        int i = tid + it * 256;
        int r = i >> 5, c4 = (i & 31) << 2;
        int gr = row0 + r;
        float4 v = (gr < N) ? A4[(size_t)gr * 32 + (i & 31)] : make_float4(0.f, 0.f, 0.f, 0.f);
        uint2 hi, lo;
        hi.x = pack_bf16x2(v.x, v.y);
        hi.y = pack_bf16x2(v.z, v.w);
        float rx = v.x - __bfloat162float(__float2bfloat16_rn(v.x));
        float ry = v.y - __bfloat162float(__float2bfloat16_rn(v.y));
        float rz = v.z - __bfloat162float(__float2bfloat16_rn(v.z));
        float rw = v.w - __bfloat162float(__float2bfloat16_rn(v.w));
        lo.x = pack_bf16x2(rx, ry);
        lo.y = pack_bf16x2(rz, rw);
        uint32_t off = (uint32_t)(r * TROWB + c4 * 2);
        *(uint2*)(smem + OFF_XHI + off) = hi;
        *(uint2*)(smem + OFF_XLO + off) = lo;
    }
    const uint2* WH2 = (const uint2*)wth;
    const uint2* WL2 = (const uint2*)wtl;
#pragma unroll
    for (int it = 0; it < 16; it++) {
        int i = tid + it * 256;
        int r = i >> 5, c4 = (i & 31) << 2;
        uint32_t off = (uint32_t)(r * TROWB + c4 * 2);
        *(uint2*)(smem + OFF_WHI + off) = WH2[i];
        *(uint2*)(smem + OFF_WLO + off) = WL2[i];
    }
    __syncthreads();

    int warp_m = wid & 3;
    int warp_n = wid >> 2;       // == head
    int m0 = warp_m * 32;
    int n0 = warp_n * 64;

    float acc[2][8][4];
#pragma unroll
    for (int mt = 0; mt < 2; mt++)
#pragma unroll
        for (int nt = 0; nt < 8; nt++)
#pragma unroll
            for (int q = 0; q < 4; q++) acc[mt][nt][q] = 0.f;

    int a_row_in = (lane & 7) + ((lane >> 3) & 1) * 8;
    int a_koff = (lane >> 4) * 16;
    int b_row_in = (lane & 7) + ((lane >> 4) & 1) * 8;
    int b_koff = ((lane >> 3) & 1) * 16;

#pragma unroll
    for (int t = 0; t < 3; t++) {
        uint32_t abase = sb + ((t == 2) ? OFF_XLO : OFF_XHI);
        uint32_t bbase = sb + ((t == 1) ? OFF_WLO : OFF_WHI);
#pragma unroll
        for (int ks = 0; ks < 8; ks++) {
            int kb = ks * 32;
            uint32_t afr[2][4];
#pragma unroll
            for (int mt = 0; mt < 2; mt++) {
                uint32_t ad = abase + (uint32_t)((m0 + mt * 16 + a_row_in) * TROWB + kb + a_koff);
                ldsm4(ad, afr[mt][0], afr[mt][1], afr[mt][2], afr[mt][3]);
            }
            uint32_t bfr[4][4];
#pragma unroll
            for (int pt = 0; pt < 4; pt++) {
                uint32_t bd = bbase + (uint32_t)((n0 + pt * 16 + b_row_in) * TROWB + kb + b_koff);
                ldsm4(bd, bfr[pt][0], bfr[pt][1], bfr[pt][2], bfr[pt][3]);
            }
#pragma unroll
            for (int mt = 0; mt < 2; mt++)
#pragma unroll
                for (int nt = 0; nt < 8; nt++)
                    mma16816(acc[mt][nt], afr[mt], bfr[nt >> 1][(nt & 1) * 2],
                             bfr[nt >> 1][(nt & 1) * 2 + 1]);
        }
    }

    // epilogue: fp16 H store + fused attention-logit dots (this warp's head)
    const float* sAS = (const float*)(smem + OFF_AS);
    const float* sAD = (const float*)(smem + OFF_AD);
    float ss[2][2] = {{0.f, 0.f}, {0.f, 0.f}};
    float dd[2][2] = {{0.f, 0.f}, {0.f, 0.f}};
#pragma unroll
    for (int nt = 0; nt < 8; nt++) {
        int col = n0 + nt * 8 + ((lane & 3) << 1);
        float as0 = sAS[col], as1 = sAS[col + 1];
        float ad0 = sAD[col], ad1 = sAD[col + 1];
#pragma unroll
        for (int mt = 0; mt < 2; mt++) {
            float c0 = acc[mt][nt][0], c1 = acc[mt][nt][1];
            float c2 = acc[mt][nt][2], c3 = acc[mt][nt][3];
            int r0 = row0 + m0 + mt * 16 + (lane >> 2);
            if (r0 < N) *(__half2*)(g_hh + (size_t)r0 * F + col) = __floats2half2_rn(c0, c1);
            if (r0 + 8 < N)
                *(__half2*)(g_hh + (size_t)(r0 + 8) * F + col) = __floats2half2_rn(c2, c3);
            ss[mt][0] += c0 * as0 + c1 * as1;
            ss[mt][1] += c2 * as0 + c3 * as1;
            dd[mt][0] += c0 * ad0 + c1 * ad1;
            dd[mt][1] += c2 * ad0 + c3 * ad1;
        }
    }
#pragma unroll
    for (int mt = 0; mt < 2; mt++)
#pragma unroll
        for (int rh = 0; rh < 2; rh++) {
            ss[mt][rh] += __shfl_xor_sync(0xffffffffu, ss[mt][rh], 1);
            ss[mt][rh] += __shfl_xor_sync(0xffffffffu, ss[mt][rh], 2);
            dd[mt][rh] += __shfl_xor_sync(0xffffffffu, dd[mt][rh], 1);
            dd[mt][rh] += __shfl_xor_sync(0xffffffffu, dd[mt][rh], 2);
        }
    if ((lane & 3) == 0) {
#pragma unroll
        for (int mt = 0; mt < 2; mt++)
#pragma unroll
            for (int rh = 0; rh < 2; rh++) {
                int m = row0 + m0 + mt * 16 + rh * 8 + (lane >> 2);
                if (m < N) {
                    g_als[m * NHEAD + warp_n] = ss[mt][rh];
                    g_ald[m * NHEAD + warp_n] = dd[mt][rh];
                }
            }
    }
}

// ---------------- fused CSR aggregation (fp16 gather, fp32 accumulate) ----------
// fuse_lin: apply output head instead of storing feat (layer 3).
__global__ void k_aggregate(const float* __restrict__ bias, int residual, int fuse_lin,
                            const float* __restrict__ lin_w, const float* __restrict__ lin_b,
                            float* __restrict__ out, int N) {
    int d = (blockIdx.x * blockDim.x + threadIdx.x) >> 5;
    if (d >= N) return;
    int lane = threadIdx.x & 31;
    int head = lane >> 4;

    float ald = g_ald[d * NHEAD + head];
    int beg = g_rowptr[d], end = g_rowptr[d + 1];

    float4 acc = make_float4(0.f, 0.f, 0.f, 0.f);
    float sum = 0.f;
    const uint2* H2 = (const uint2*)g_hh;   // 32 uint2 per row (4 halfs each)

    int j = beg;
    for (; j + 4 <= end; j += 4) {
        int s0 = g_esrc[j], s1 = g_esrc[j + 1], s2 = g_esrc[j + 2], s3 = g_esrc[j + 3];
        float e0 = __expf(leaky(g_als[s0 * NHEAD + head] + ald));
        float e1 = __expf(leaky(g_als[s1 * NHEAD + head] + ald));
        float e2 = __expf(leaky(g_als[s2 * NHEAD + head] + ald));
        float e3 = __expf(leaky(g_als[s3 * NHEAD + head] + ald));
        uint2 r0 = __ldg(H2 + (size_t)s0 * 32 + lane);
        uint2 r1 = __ldg(H2 + (size_t)s1 * 32 + lane);
        uint2 r2 = __ldg(H2 + (size_t)s2 * 32 + lane);
        uint2 r3 = __ldg(H2 + (size_t)s3 * 32 + lane);
        sum += (e0 + e1) + (e2 + e3);
        float2 a0 = __half22float2(*(__half2*)&r0.x), b0 = __half22float2(*(__half2*)&r0.y);
        float2 a1 = __half22float2(*(__half2*)&r1.x), b1 = __half22float2(*(__half2*)&r1.y);
        float2 a2 = __half22float2(*(__half2*)&r2.x), b2 = __half22float2(*(__half2*)&r2.y);
        float2 a3 = __half22float2(*(__half2*)&r3.x), b3 = __half22float2(*(__half2*)&r3.y);
        acc.x += e0 * a0.x + e1 * a1.x + e2 * a2.x + e3 * a3.x;
        acc.y += e0 * a0.y + e1 * a1.y + e2 * a2.y + e3 * a3.y;
        acc.z += e0 * b0.x + e1 * b1.x + e2 * b2.x + e3 * b3.x;
        acc.w += e0 * b0.y + e1 * b1.y + e2 * b2.y + e3 * b3.y;
    }
    for (; j < end; j++) {
        int s = g_esrc[j];
        float ex = __expf(leaky(g_als[s * NHEAD + head] + ald));
        uint2 r = __ldg(H2 + (size_t)s * 32 + lane);
        float2 a = __half22float2(*(__half2*)&r.x), b = __half22float2(*(__half2*)&r.y);
        sum += ex;
        acc.x += ex * a.x; acc.y += ex * a.y;
        acc.z += ex * b.x; acc.w += ex * b.y;
    }

    float inv = 1.f / sum;
    float4 b4 = __ldg(((const float4*)bias) + lane);
    float4 v;
    v.x = acc.x * inv + b4.x; v.y = acc.y * inv + b4.y;
    v.z = acc.z * inv + b4.z; v.w = acc.w * inv + b4.w;
    if (residual) {
        float4 f = ((const float4*)g_feat)[(size_t)d * 32 + lane];
        v.x += f.x; v.y += f.y; v.z += f.z; v.w += f.w;
    }
    v.x = leaky(v.x); v.y = leaky(v.y); v.z = leaky(v.z); v.w = leaky(v.w);
    if (!fuse_lin) {
        ((float4*)g_feat)[(size_t)d * 32 + lane] = v;
    } else {
        float4 wv = __ldg(((const float4*)lin_w) + lane);
        float s = v.x * wv.x + v.y * wv.y + v.z * wv.z + v.w * wv.w;
#pragma unroll
        for (int o = 16; o; o >>= 1) s += __shfl_xor_sync(0xffffffffu, s, o);
        if (lane == 0) out[d] = s + __ldg(lin_b);
    }
}

// ---------------- host ----------------
extern "C" void kernel_launch(void* const* d_in, const int* in_sizes, int n_in,
                              void* d_out, int out_size) {
    const float* x = (const float*)d_in[0];
    const int* ei = (const int*)d_in[1];
    const float* W[3] = {(const float*)d_in[2], (const float*)d_in[6], (const float*)d_in[10]};
    const float* as[3] = {(const float*)d_in[3], (const float*)d_in[7], (const float*)d_in[11]};
    const float* ad[3] = {(const float*)d_in[4], (const float*)d_in[8], (const float*)d_in[12]};
    const float* bs[3] = {(const float*)d_in[5], (const float*)d_in[9], (const float*)d_in[13]};
    const float* lin_w = (const float*)d_in[14];
    const float* lin_b = (const float*)d_in[15];

    int N = in_sizes[0] / F;
    int E = in_sizes[1] / 2;
    int EE = E + N;
    int nb = (N + SCANB - 1) / SCANB;

    static bool attr_done = false;
    if (!attr_done) {
        cudaFuncSetAttribute(k_gemm_tc, cudaFuncAttributeMaxDynamicSharedMemorySize,
                             GEMM_SMEM_TOTAL);
        attr_done = true;
    }

    float* feat_ptr = nullptr;
    cudaGetSymbolAddress((void**)&feat_ptr, g_feat);
    int* cnt_ptr = nullptr;
    cudaGetSymbolAddress((void**)&cnt_ptr, g_cnt);
    __nv_bfloat16* wth_ptr = nullptr;
    cudaGetSymbolAddress((void**)&wth_ptr, g_wth);
    __nv_bfloat16* wtl_ptr = nullptr;
    cudaGetSymbolAddress((void**)&wtl_ptr, g_wtl);

    const int TB = 256;
    int gemm_blocks = (N + TM - 1) / TM;
    int warpN_blocks = (N * 32 + TB - 1) / TB;
    int edge_blocks = (EE + TB - 1) / TB;
    int prep_blocks = (3 * F * F + TB - 1) / TB;

    // ---- CSR build + W prep ----
    cudaMemsetAsync(cnt_ptr, 0, N * sizeof(int));
    k_build_hist<<<edge_blocks, TB>>>(ei, E, N);
    k_scan1<<<nb, SCANB>>>(N);
    k_scan23<<<nb, SCANB>>>(N, EE, nb);
    k_fill<<<edge_blocks, TB>>>(EE);
    k_prep_w3<<<prep_blocks, TB>>>(W[0], W[1], W[2]);

    // ---- 3 GAT layers ----
    for (int l = 0; l < 3; l++) {
        const float* in = (l == 0) ? x : feat_ptr;
        k_gemm_tc<<<gemm_blocks, 256, GEMM_SMEM_TOTAL>>>(
            in, wth_ptr + (size_t)l * F * F, wtl_ptr + (size_t)l * F * F,
            as[l], ad[l], N);
        k_aggregate<<<warpN_blocks, TB>>>(bs[l], l > 0, l == 2, lin_w, lin_b,
                                          (float*)d_out, N);
    }
}

// round 7
// speedup vs baseline: 3.0981x; 1.0103x over previous
#include <cuda_runtime.h>
#include <cuda_bf16.h>
#include <cuda_fp16.h>
#include <cstdint>

#define MAXN 50000
#define MAXE 800000
#define MAXEE (MAXN + MAXE)
#define F 128
#define NHEAD 2
#define NEG 0.2f
#define SCANB 256
#define TM 128

// ---------------- scratch (device globals; no allocation) ----------------
__device__ __half g_hh[(size_t)MAXN * F];   // h in fp16 (gather path)
__device__ float g_feat[(size_t)MAXN * F];
__device__ float g_als[MAXN * NHEAD];
__device__ float g_ald[MAXN * NHEAD];
__device__ int g_rank[MAXEE];               // edge rank within its dst segment
__device__ int g_cnt[MAXN];
__device__ int g_incl[MAXN];
__device__ int g_bsum[(MAXN + SCANB - 1) / SCANB];
__device__ int g_rowptr[MAXN + 1];
__device__ int g_esrc[MAXEE];
__device__ __nv_bfloat16 g_wth[3][F * F];   // W^T hi, [n][k]
__device__ __nv_bfloat16 g_wtl[3][F * F];   // W^T lo, [n][k]

__device__ __forceinline__ float leaky(float x) { return x > 0.f ? x : NEG * x; }

__device__ __forceinline__ uint32_t smem_u32(const void* p) {
    uint32_t a;
    asm("{ .reg .u64 t; cvta.to.shared.u64 t, %1; cvt.u32.u64 %0, t; }" : "=r"(a) : "l"(p));
    return a;
}

// ---------------- graph build ----------------
// histogram + per-edge rank in one pass (g_cnt pre-zeroed). atomicAdd's return
// value IS the edge's rank within its destination segment.
__global__ void k_build_hist(const int* __restrict__ ei, int E, int N) {
    int i = blockIdx.x * blockDim.x + threadIdx.x;
    int EE = E + N;
    if (i >= EE) return;
    int d = (i < E) ? ei[E + i] : (i - E);
    g_rank[i] = atomicAdd(&g_cnt[d], 1);
}
__global__ void k_scan1(int N) {
    __shared__ int sm[SCANB];
    int i = blockIdx.x * SCANB + threadIdx.x;
    int v = (i < N) ? g_cnt[i] : 0;
    sm[threadIdx.x] = v;
    __syncthreads();
#pragma unroll
    for (int o = 1; o < SCANB; o <<= 1) {
        int t = (threadIdx.x >= o) ? sm[threadIdx.x - o] : 0;
        __syncthreads();
        sm[threadIdx.x] += t;
        __syncthreads();
    }
    if (i < N) g_incl[i] = sm[threadIdx.x];
    if (threadIdx.x == SCANB - 1) g_bsum[blockIdx.x] = sm[SCANB - 1];
}
// each block redundantly scans the <=256 block sums, then finishes rowptr.
__global__ void k_scan23(int N, int EE, int nb) {
    __shared__ int sm[SCANB];
    int v = (threadIdx.x < nb) ? g_bsum[threadIdx.x] : 0;
    sm[threadIdx.x] = v;
    __syncthreads();
#pragma unroll
    for (int o = 1; o < SCANB; o <<= 1) {
        int t = (threadIdx.x >= o) ? sm[threadIdx.x - o] : 0;
        __syncthreads();
        sm[threadIdx.x] += t;
        __syncthreads();
    }
    int bid = blockIdx.x;
    int boff = sm[bid] - g_bsum[bid];   // exclusive prefix of this block
    int i = bid * SCANB + threadIdx.x;
    if (i < N) g_rowptr[i] = g_incl[i] - g_cnt[i] + boff;
    if (i == 0) g_rowptr[N] = EE;
}
// atomic-free CSR fill using precomputed ranks.
__global__ void k_fill(const int* __restrict__ ei, int E, int N) {
    int i = blockIdx.x * blockDim.x + threadIdx.x;
    int EE = E + N;
    if (i >= EE) return;
    int s, d;
    if (i < E) { s = ei[i]; d = ei[E + i]; }
    else       { s = i - E; d = i - E; }
    g_esrc[g_rowptr[d] + g_rank[i]] = s;
}

// ---------------- W prep: transpose + hi/lo bf16 split, all 3 layers ----------------
__global__ void k_prep_w3(const float* __restrict__ W0, const float* __restrict__ W1,
                          const float* __restrict__ W2) {
    int i = blockIdx.x * blockDim.x + threadIdx.x;
    if (i >= 3 * F * F) return;
    int l = i / (F * F), j = i % (F * F);
    const float* W = (l == 0) ? W0 : ((l == 1) ? W1 : W2);
    int k = j / F, n = j % F;
    float v = W[j];
    __nv_bfloat16 h = __float2bfloat16_rn(v);
    float r = v - __bfloat162float(h);
    g_wth[l][n * F + k] = h;
    g_wtl[l][n * F + k] = __float2bfloat16_rn(r);
}

// ---------------- mma.sync GEMM + fused attention logits ----------------
#define TSTRIDE 136
#define TROWB (TSTRIDE * 2)
#define TILE_BYTES (128 * TROWB)
#define OFF_AS 0
#define OFF_AD 512
#define OFF_XHI 1024
#define OFF_XLO (OFF_XHI + TILE_BYTES)
#define OFF_WHI (OFF_XLO + TILE_BYTES)
#define OFF_WLO (OFF_WHI + TILE_BYTES)
#define GEMM_SMEM_TOTAL (OFF_WLO + TILE_BYTES)

__device__ __forceinline__ void ldsm4(uint32_t addr, uint32_t& r0, uint32_t& r1,
                                      uint32_t& r2, uint32_t& r3) {
    asm volatile("ldmatrix.sync.aligned.m8n8.x4.shared.b16 {%0,%1,%2,%3}, [%4];"
                 : "=r"(r0), "=r"(r1), "=r"(r2), "=r"(r3) : "r"(addr));
}
__device__ __forceinline__ void mma16816(float* c, const uint32_t* a, uint32_t b0, uint32_t b1) {
    asm volatile(
        "mma.sync.aligned.m16n8k16.row.col.f32.bf16.bf16.f32 "
        "{%0,%1,%2,%3}, {%4,%5,%6,%7}, {%8,%9}, {%0,%1,%2,%3};"
        : "+f"(c[0]), "+f"(c[1]), "+f"(c[2]), "+f"(c[3])
        : "r"(a[0]), "r"(a[1]), "r"(a[2]), "r"(a[3]), "r"(b0), "r"(b1));
}
__device__ __forceinline__ uint32_t pack_bf16x2(float a, float b) {
    __nv_bfloat16 ha = __float2bfloat16_rn(a), hb = __float2bfloat16_rn(b);
    return (uint32_t)__bfloat16_as_ushort(ha) | ((uint32_t)__bfloat16_as_ushort(hb) << 16);
}

__global__ void __launch_bounds__(256, 1)
k_gemm_tc(const float* __restrict__ A, const __nv_bfloat16* __restrict__ wth,
          const __nv_bfloat16* __restrict__ wtl, const float* __restrict__ a_src,
          const float* __restrict__ a_dst, int N) {
    extern __shared__ char smem[];
    uint32_t sb = smem_u32(smem);
    int tid = threadIdx.x;
    int wid = tid >> 5, lane = tid & 31;
    int row0 = blockIdx.x * TM;

    if (tid < F) {
        *(float*)(smem + OFF_AS + tid * 4) = __ldg(a_src + tid);
        *(float*)(smem + OFF_AD + tid * 4) = __ldg(a_dst + tid);
    }

    const float4* A4 = (const float4*)A;
#pragma unroll
    for (int it = 0; it < 16; it++) {
        int i = tid + it * 256;
        int r = i >> 5, c4 = (i & 31) << 2;
        int gr = row0 + r;
        float4 v = (gr < N) ? A4[(size_t)gr * 32 + (i & 31)] : make_float4(0.f, 0.f, 0.f, 0.f);
        uint2 hi, lo;
        hi.x = pack_bf16x2(v.x, v.y);
        hi.y = pack_bf16x2(v.z, v.w);
        float rx = v.x - __bfloat162float(__float2bfloat16_rn(v.x));
        float ry = v.y - __bfloat162float(__float2bfloat16_rn(v.y));
        float rz = v.z - __bfloat162float(__float2bfloat16_rn(v.z));
        float rw = v.w - __bfloat162float(__float2bfloat16_rn(v.w));
        lo.x = pack_bf16x2(rx, ry);
        lo.y = pack_bf16x2(rz, rw);
        uint32_t off = (uint32_t)(r * TROWB + c4 * 2);
        *(uint2*)(smem + OFF_XHI + off) = hi;
        *(uint2*)(smem + OFF_XLO + off) = lo;
    }
    const uint2* WH2 = (const uint2*)wth;
    const uint2* WL2 = (const uint2*)wtl;
#pragma unroll
    for (int it = 0; it < 16; it++) {
        int i = tid + it * 256;
        int r = i >> 5, c4 = (i & 31) << 2;
        uint32_t off = (uint32_t)(r * TROWB + c4 * 2);
        *(uint2*)(smem + OFF_WHI + off) = WH2[i];
        *(uint2*)(smem + OFF_WLO + off) = WL2[i];
    }
    __syncthreads();

    int warp_m = wid & 3;
    int warp_n = wid >> 2;       // == head
    int m0 = warp_m * 32;
    int n0 = warp_n * 64;

    float acc[2][8][4];
#pragma unroll
    for (int mt = 0; mt < 2; mt++)
#pragma unroll
        for (int nt = 0; nt < 8; nt++)
#pragma unroll
            for (int q = 0; q < 4; q++) acc[mt][nt][q] = 0.f;

    int a_row_in = (lane & 7) + ((lane >> 3) & 1) * 8;
    int a_koff = (lane >> 4) * 16;
    int b_row_in = (lane & 7) + ((lane >> 4) & 1) * 8;
    int b_koff = ((lane >> 3) & 1) * 16;

#pragma unroll
    for (int t = 0; t < 3; t++) {
        uint32_t abase = sb + ((t == 2) ? OFF_XLO : OFF_XHI);
        uint32_t bbase = sb + ((t == 1) ? OFF_WLO : OFF_WHI);
#pragma unroll
        for (int ks = 0; ks < 8; ks++) {
            int kb = ks * 32;
            uint32_t afr[2][4];
#pragma unroll
            for (int mt = 0; mt < 2; mt++) {
                uint32_t ad = abase + (uint32_t)((m0 + mt * 16 + a_row_in) * TROWB + kb + a_koff);
                ldsm4(ad, afr[mt][0], afr[mt][1], afr[mt][2], afr[mt][3]);
            }
            uint32_t bfr[4][4];
#pragma unroll
            for (int pt = 0; pt < 4; pt++) {
                uint32_t bd = bbase + (uint32_t)((n0 + pt * 16 + b_row_in) * TROWB + kb + b_koff);
                ldsm4(bd, bfr[pt][0], bfr[pt][1], bfr[pt][2], bfr[pt][3]);
            }
#pragma unroll
            for (int mt = 0; mt < 2; mt++)
#pragma unroll
                for (int nt = 0; nt < 8; nt++)
                    mma16816(acc[mt][nt], afr[mt], bfr[nt >> 1][(nt & 1) * 2],
                             bfr[nt >> 1][(nt & 1) * 2 + 1]);
        }
    }

    // epilogue: fp16 H store + fused attention-logit dots (this warp's head)
    const float* sAS = (const float*)(smem + OFF_AS);
    const float* sAD = (const float*)(smem + OFF_AD);
    float ss[2][2] = {{0.f, 0.f}, {0.f, 0.f}};
    float dd[2][2] = {{0.f, 0.f}, {0.f, 0.f}};
#pragma unroll
    for (int nt = 0; nt < 8; nt++) {
        int col = n0 + nt * 8 + ((lane & 3) << 1);
        float as0 = sAS[col], as1 = sAS[col + 1];
        float ad0 = sAD[col], ad1 = sAD[col + 1];
#pragma unroll
        for (int mt = 0; mt < 2; mt++) {
            float c0 = acc[mt][nt][0], c1 = acc[mt][nt][1];
            float c2 = acc[mt][nt][2], c3 = acc[mt][nt][3];
            int r0 = row0 + m0 + mt * 16 + (lane >> 2);
            if (r0 < N) *(__half2*)(g_hh + (size_t)r0 * F + col) = __floats2half2_rn(c0, c1);
            if (r0 + 8 < N)
                *(__half2*)(g_hh + (size_t)(r0 + 8) * F + col) = __floats2half2_rn(c2, c3);
            ss[mt][0] += c0 * as0 + c1 * as1;
            ss[mt][1] += c2 * as0 + c3 * as1;
            dd[mt][0] += c0 * ad0 + c1 * ad1;
            dd[mt][1] += c2 * ad0 + c3 * ad1;
        }
    }
#pragma unroll
    for (int mt = 0; mt < 2; mt++)
#pragma unroll
        for (int rh = 0; rh < 2; rh++) {
            ss[mt][rh] += __shfl_xor_sync(0xffffffffu, ss[mt][rh], 1);
            ss[mt][rh] += __shfl_xor_sync(0xffffffffu, ss[mt][rh], 2);
            dd[mt][rh] += __shfl_xor_sync(0xffffffffu, dd[mt][rh], 1);
            dd[mt][rh] += __shfl_xor_sync(0xffffffffu, dd[mt][rh], 2);
        }
    if ((lane & 3) == 0) {
#pragma unroll
        for (int mt = 0; mt < 2; mt++)
#pragma unroll
            for (int rh = 0; rh < 2; rh++) {
                int m = row0 + m0 + mt * 16 + rh * 8 + (lane >> 2);
                if (m < N) {
                    g_als[m * NHEAD + warp_n] = ss[mt][rh];
                    g_ald[m * NHEAD + warp_n] = dd[mt][rh];
                }
            }
    }
}

// ---------------- fused CSR aggregation (fp16 gather, fp32 accumulate) ----------
__global__ void k_aggregate(const float* __restrict__ bias, int residual, int fuse_lin,
                            const float* __restrict__ lin_w, const float* __restrict__ lin_b,
                            float* __restrict__ out, int N) {
    int d = (blockIdx.x * blockDim.x + threadIdx.x) >> 5;
    if (d >= N) return;
    int lane = threadIdx.x & 31;
    int head = lane >> 4;

    float ald = g_ald[d * NHEAD + head];
    int beg = g_rowptr[d], end = g_rowptr[d + 1];

    float4 acc = make_float4(0.f, 0.f, 0.f, 0.f);
    float sum = 0.f;
    const uint2* H2 = (const uint2*)g_hh;

    int j = beg;
    for (; j + 4 <= end; j += 4) {
        int s0 = g_esrc[j], s1 = g_esrc[j + 1], s2 = g_esrc[j + 2], s3 = g_esrc[j + 3];
        float e0 = __expf(leaky(g_als[s0 * NHEAD + head] + ald));
        float e1 = __expf(leaky(g_als[s1 * NHEAD + head] + ald));
        float e2 = __expf(leaky(g_als[s2 * NHEAD + head] + ald));
        float e3 = __expf(leaky(g_als[s3 * NHEAD + head] + ald));
        uint2 r0 = __ldg(H2 + (size_t)s0 * 32 + lane);
        uint2 r1 = __ldg(H2 + (size_t)s1 * 32 + lane);
        uint2 r2 = __ldg(H2 + (size_t)s2 * 32 + lane);
        uint2 r3 = __ldg(H2 + (size_t)s3 * 32 + lane);
        sum += (e0 + e1) + (e2 + e3);
        float2 a0 = __half22float2(*(__half2*)&r0.x), b0 = __half22float2(*(__half2*)&r0.y);
        float2 a1 = __half22float2(*(__half2*)&r1.x), b1 = __half22float2(*(__half2*)&r1.y);
        float2 a2 = __half22float2(*(__half2*)&r2.x), b2 = __half22float2(*(__half2*)&r2.y);
        float2 a3 = __half22float2(*(__half2*)&r3.x), b3 = __half22float2(*(__half2*)&r3.y);
        acc.x += e0 * a0.x + e1 * a1.x + e2 * a2.x + e3 * a3.x;
        acc.y += e0 * a0.y + e1 * a1.y + e2 * a2.y + e3 * a3.y;
        acc.z += e0 * b0.x + e1 * b1.x + e2 * b2.x + e3 * b3.x;
        acc.w += e0 * b0.y + e1 * b1.y + e2 * b2.y + e3 * b3.y;
    }
    for (; j < end; j++) {
        int s = g_esrc[j];
        float ex = __expf(leaky(g_als[s * NHEAD + head] + ald));
        uint2 r = __ldg(H2 + (size_t)s * 32 + lane);
        float2 a = __half22float2(*(__half2*)&r.x), b = __half22float2(*(__half2*)&r.y);
        sum += ex;
        acc.x += ex * a.x; acc.y += ex * a.y;
        acc.z += ex * b.x; acc.w += ex * b.y;
    }

    float inv = 1.f / sum;
    float4 b4 = __ldg(((const float4*)bias) + lane);
    float4 v;
    v.x = acc.x * inv + b4.x; v.y = acc.y * inv + b4.y;
    v.z = acc.z * inv + b4.z; v.w = acc.w * inv + b4.w;
    if (residual) {
        float4 f = ((const float4*)g_feat)[(size_t)d * 32 + lane];
        v.x += f.x; v.y += f.y; v.z += f.z; v.w += f.w;
    }
    v.x = leaky(v.x); v.y = leaky(v.y); v.z = leaky(v.z); v.w = leaky(v.w);
    if (!fuse_lin) {
        ((float4*)g_feat)[(size_t)d * 32 + lane] = v;
    } else {
        float4 wv = __ldg(((const float4*)lin_w) + lane);
        float s = v.x * wv.x + v.y * wv.y + v.z * wv.z + v.w * wv.w;
#pragma unroll
        for (int o = 16; o; o >>= 1) s += __shfl_xor_sync(0xffffffffu, s, o);
        if (lane == 0) out[d] = s + __ldg(lin_b);
    }
}

// ---------------- host ----------------
extern "C" void kernel_launch(void* const* d_in, const int* in_sizes, int n_in,
                              void* d_out, int out_size) {
    const float* x = (const float*)d_in[0];
    const int* ei = (const int*)d_in[1];
    const float* W[3] = {(const float*)d_in[2], (const float*)d_in[6], (const float*)d_in[10]};
    const float* as[3] = {(const float*)d_in[3], (const float*)d_in[7], (const float*)d_in[11]};
    const float* ad[3] = {(const float*)d_in[4], (const float*)d_in[8], (const float*)d_in[12]};
    const float* bs[3] = {(const float*)d_in[5], (const float*)d_in[9], (const float*)d_in[13]};
    const float* lin_w = (const float*)d_in[14];
    const float* lin_b = (const float*)d_in[15];

    int N = in_sizes[0] / F;
    int E = in_sizes[1] / 2;
    int EE = E + N;
    int nb = (N + SCANB - 1) / SCANB;

    static bool attr_done = false;
    if (!attr_done) {
        cudaFuncSetAttribute(k_gemm_tc, cudaFuncAttributeMaxDynamicSharedMemorySize,
                             GEMM_SMEM_TOTAL);
        attr_done = true;
    }

    float* feat_ptr = nullptr;
    cudaGetSymbolAddress((void**)&feat_ptr, g_feat);
    int* cnt_ptr = nullptr;
    cudaGetSymbolAddress((void**)&cnt_ptr, g_cnt);
    __nv_bfloat16* wth_ptr = nullptr;
    cudaGetSymbolAddress((void**)&wth_ptr, g_wth);
    __nv_bfloat16* wtl_ptr = nullptr;
    cudaGetSymbolAddress((void**)&wtl_ptr, g_wtl);

    const int TB = 256;
    int gemm_blocks = (N + TM - 1) / TM;
    int warpN_blocks = (N * 32 + TB - 1) / TB;
    int edge_blocks = (EE + TB - 1) / TB;
    int prep_blocks = (3 * F * F + TB - 1) / TB;

    // ---- CSR build + W prep ----
    cudaMemsetAsync(cnt_ptr, 0, N * sizeof(int));
    k_build_hist<<<edge_blocks, TB>>>(ei, E, N);
    k_scan1<<<nb, SCANB>>>(N);
    k_scan23<<<nb, SCANB>>>(N, EE, nb);
    k_fill<<<edge_blocks, TB>>>(ei, E, N);
    k_prep_w3<<<prep_blocks, TB>>>(W[0], W[1], W[2]);

    // ---- 3 GAT layers ----
    for (int l = 0; l < 3; l++) {
        const float* in = (l == 0) ? x : feat_ptr;
        k_gemm_tc<<<gemm_blocks, 256, GEMM_SMEM_TOTAL>>>(
            in, wth_ptr + (size_t)l * F * F, wtl_ptr + (size_t)l * F * F,
            as[l], ad[l], N);
        k_aggregate<<<warpN_blocks, TB>>>(bs[l], l > 0, l == 2, lin_w, lin_b,
                                          (float*)d_out, N);
    }
}

// round 8
// speedup vs baseline: 3.1746x; 1.0247x over previous
#include <cuda_runtime.h>
#include <cuda_bf16.h>
#include <cuda_fp16.h>
#include <cstdint>

#define MAXN 50000
#define MAXE 800000
#define MAXEE (MAXN + MAXE)
#define F 128
#define NHEAD 2
#define NEG 0.2f
#define SCANB 256
#define TM 128

// ---------------- scratch (device globals; no allocation) ----------------
__device__ __half g_hh[(size_t)MAXN * F];   // h in fp16 (gather path)
__device__ float g_feat[(size_t)MAXN * F];
__device__ float g_als[MAXN * NHEAD];
__device__ float g_ald[MAXN * NHEAD];
__device__ int g_rank[MAXEE];               // edge rank within its dst segment
__device__ int g_cnt[MAXN];
__device__ int g_incl[MAXN];
__device__ int g_bsum[(MAXN + SCANB - 1) / SCANB];
__device__ int g_rowptr[MAXN + 1];
__device__ int g_esrc[MAXEE];
__device__ __nv_bfloat16 g_wth[3][F * F];   // W^T hi, [n][k]
__device__ __nv_bfloat16 g_wtl[3][F * F];   // W^T lo, [n][k]

__device__ __forceinline__ float leaky(float x) { return x > 0.f ? x : NEG * x; }

__device__ __forceinline__ uint32_t smem_u32(const void* p) {
    uint32_t a;
    asm("{ .reg .u64 t; cvta.to.shared.u64 t, %1; cvt.u32.u64 %0, t; }" : "=r"(a) : "l"(p));
    return a;
}

// ---------------- graph build ----------------
// histogram + per-edge rank; 4 edges per thread, int4 loads (MLP=4).
__global__ void k_build_hist(const int* __restrict__ ei, int E, int N) {
    int base = (blockIdx.x * blockDim.x + threadIdx.x) * 4;
    int EE = E + N;
    if (base >= EE) return;
    if (base + 3 < E) {
        int4 d = *(const int4*)(ei + E + base);
        int4 r;
        r.x = atomicAdd(&g_cnt[d.x], 1);
        r.y = atomicAdd(&g_cnt[d.y], 1);
        r.z = atomicAdd(&g_cnt[d.z], 1);
        r.w = atomicAdd(&g_cnt[d.w], 1);
        *(int4*)(g_rank + base) = r;
    } else {
#pragma unroll
        for (int q = 0; q < 4; q++) {
            int i = base + q;
            if (i >= EE) break;
            int d = (i < E) ? ei[E + i] : (i - E);
            g_rank[i] = atomicAdd(&g_cnt[d], 1);
        }
    }
}
__global__ void k_scan1(int N) {
    __shared__ int sm[SCANB];
    int i = blockIdx.x * SCANB + threadIdx.x;
    int v = (i < N) ? g_cnt[i] : 0;
    sm[threadIdx.x] = v;
    __syncthreads();
#pragma unroll
    for (int o = 1; o < SCANB; o <<= 1) {
        int t = (threadIdx.x >= o) ? sm[threadIdx.x - o] : 0;
        __syncthreads();
        sm[threadIdx.x] += t;
        __syncthreads();
    }
    if (i < N) g_incl[i] = sm[threadIdx.x];
    if (threadIdx.x == SCANB - 1) g_bsum[blockIdx.x] = sm[SCANB - 1];
}
// each block redundantly scans the <=256 block sums, then finishes rowptr.
__global__ void k_scan23(int N, int EE, int nb) {
    __shared__ int sm[SCANB];
    int v = (threadIdx.x < nb) ? g_bsum[threadIdx.x] : 0;
    sm[threadIdx.x] = v;
    __syncthreads();
#pragma unroll
    for (int o = 1; o < SCANB; o <<= 1) {
        int t = (threadIdx.x >= o) ? sm[threadIdx.x - o] : 0;
        __syncthreads();
        sm[threadIdx.x] += t;
        __syncthreads();
    }
    int bid = blockIdx.x;
    int boff = sm[bid] - g_bsum[bid];   // exclusive prefix of this block
    int i = bid * SCANB + threadIdx.x;
    if (i < N) g_rowptr[i] = g_incl[i] - g_cnt[i] + boff;
    if (i == 0) g_rowptr[N] = EE;
}
// atomic-free CSR fill; 4 edges per thread, int4 loads.
__global__ void k_fill(const int* __restrict__ ei, int E, int N) {
    int base = (blockIdx.x * blockDim.x + threadIdx.x) * 4;
    int EE = E + N;
    if (base >= EE) return;
    if (base + 3 < E) {
        int4 s = *(const int4*)(ei + base);
        int4 d = *(const int4*)(ei + E + base);
        int4 r = *(const int4*)(g_rank + base);
        g_esrc[g_rowptr[d.x] + r.x] = s.x;
        g_esrc[g_rowptr[d.y] + r.y] = s.y;
        g_esrc[g_rowptr[d.z] + r.z] = s.z;
        g_esrc[g_rowptr[d.w] + r.w] = s.w;
    } else {
#pragma unroll
        for (int q = 0; q < 4; q++) {
            int i = base + q;
            if (i >= EE) break;
            int s, d;
            if (i < E) { s = ei[i]; d = ei[E + i]; }
            else       { s = i - E; d = i - E; }
            g_esrc[g_rowptr[d] + g_rank[i]] = s;
        }
    }
}

// ---------------- W prep: transpose + hi/lo bf16 split, all 3 layers ----------------
__global__ void k_prep_w3(const float* __restrict__ W0, const float* __restrict__ W1,
                          const float* __restrict__ W2) {
    int i = blockIdx.x * blockDim.x + threadIdx.x;
    if (i >= 3 * F * F) return;
    int l = i / (F * F), j = i % (F * F);
    const float* W = (l == 0) ? W0 : ((l == 1) ? W1 : W2);
    int k = j / F, n = j % F;
    float v = W[j];
    __nv_bfloat16 h = __float2bfloat16_rn(v);
    float r = v - __bfloat162float(h);
    g_wth[l][n * F + k] = h;
    g_wtl[l][n * F + k] = __float2bfloat16_rn(r);
}

// ---------------- mma.sync GEMM + fused attention logits ----------------
#define TSTRIDE 136
#define TROWB (TSTRIDE * 2)
#define TILE_BYTES (128 * TROWB)
#define OFF_AS 0
#define OFF_AD 512
#define OFF_XHI 1024
#define OFF_XLO (OFF_XHI + TILE_BYTES)
#define OFF_WHI (OFF_XLO + TILE_BYTES)
#define OFF_WLO (OFF_WHI + TILE_BYTES)
#define GEMM_SMEM_TOTAL (OFF_WLO + TILE_BYTES)

__device__ __forceinline__ void ldsm4(uint32_t addr, uint32_t& r0, uint32_t& r1,
                                      uint32_t& r2, uint32_t& r3) {
    asm volatile("ldmatrix.sync.aligned.m8n8.x4.shared.b16 {%0,%1,%2,%3}, [%4];"
                 : "=r"(r0), "=r"(r1), "=r"(r2), "=r"(r3) : "r"(addr));
}
__device__ __forceinline__ void mma16816(float* c, const uint32_t* a, uint32_t b0, uint32_t b1) {
    asm volatile(
        "mma.sync.aligned.m16n8k16.row.col.f32.bf16.bf16.f32 "
        "{%0,%1,%2,%3}, {%4,%5,%6,%7}, {%8,%9}, {%0,%1,%2,%3};"
        : "+f"(c[0]), "+f"(c[1]), "+f"(c[2]), "+f"(c[3])
        : "r"(a[0]), "r"(a[1]), "r"(a[2]), "r"(a[3]), "r"(b0), "r"(b1));
}
__device__ __forceinline__ uint32_t pack_bf16x2(float a, float b) {
    __nv_bfloat16 ha = __float2bfloat16_rn(a), hb = __float2bfloat16_rn(b);
    return (uint32_t)__bfloat16_as_ushort(ha) | ((uint32_t)__bfloat16_as_ushort(hb) << 16);
}

__global__ void __launch_bounds__(256, 1)
k_gemm_tc(const float* __restrict__ A, const __nv_bfloat16* __restrict__ wth,
          const __nv_bfloat16* __restrict__ wtl, const float* __restrict__ a_src,
          const float* __restrict__ a_dst, int N) {
    extern __shared__ char smem[];
    uint32_t sb = smem_u32(smem);
    int tid = threadIdx.x;
    int wid = tid >> 5, lane = tid & 31;
    int row0 = blockIdx.x * TM;

    if (tid < F) {
        *(float*)(smem + OFF_AS + tid * 4) = __ldg(a_src + tid);
        *(float*)(smem + OFF_AD + tid * 4) = __ldg(a_dst + tid);
    }

    const float4* A4 = (const float4*)A;
#pragma unroll
    for (int it = 0; it < 16; it++) {
        int i = tid + it * 256;
        int r = i >> 5, c4 = (i & 31) << 2;
        int gr = row0 + r;
        float4 v = (gr < N) ? A4[(size_t)gr * 32 + (i & 31)] : make_float4(0.f, 0.f, 0.f, 0.f);
        uint2 hi, lo;
        hi.x = pack_bf16x2(v.x, v.y);
        hi.y = pack_bf16x2(v.z, v.w);
        float rx = v.x - __bfloat162float(__float2bfloat16_rn(v.x));
        float ry = v.y - __bfloat162float(__float2bfloat16_rn(v.y));
        float rz = v.z - __bfloat162float(__float2bfloat16_rn(v.z));
        float rw = v.w - __bfloat162float(__float2bfloat16_rn(v.w));
        lo.x = pack_bf16x2(rx, ry);
        lo.y = pack_bf16x2(rz, rw);
        uint32_t off = (uint32_t)(r * TROWB + c4 * 2);
        *(uint2*)(smem + OFF_XHI + off) = hi;
        *(uint2*)(smem + OFF_XLO + off) = lo;
    }
    const uint2* WH2 = (const uint2*)wth;
    const uint2* WL2 = (const uint2*)wtl;
#pragma unroll
    for (int it = 0; it < 16; it++) {
        int i = tid + it * 256;
        int r = i >> 5, c4 = (i & 31) << 2;
        uint32_t off = (uint32_t)(r * TROWB + c4 * 2);
        *(uint2*)(smem + OFF_WHI + off) = WH2[i];
        *(uint2*)(smem + OFF_WLO + off) = WL2[i];
    }
    __syncthreads();

    int warp_m = wid & 3;
    int warp_n = wid >> 2;       // == head
    int m0 = warp_m * 32;
    int n0 = warp_n * 64;

    float acc[2][8][4];
#pragma unroll
    for (int mt = 0; mt < 2; mt++)
#pragma unroll
        for (int nt = 0; nt < 8; nt++)
#pragma unroll
            for (int q = 0; q < 4; q++) acc[mt][nt][q] = 0.f;

    int a_row_in = (lane & 7) + ((lane >> 3) & 1) * 8;
    int a_koff = (lane >> 4) * 16;
    int b_row_in = (lane & 7) + ((lane >> 4) & 1) * 8;
    int b_koff = ((lane >> 3) & 1) * 16;

#pragma unroll
    for (int t = 0; t < 3; t++) {
        uint32_t abase = sb + ((t == 2) ? OFF_XLO : OFF_XHI);
        uint32_t bbase = sb + ((t == 1) ? OFF_WLO : OFF_WHI);
#pragma unroll
        for (int ks = 0; ks < 8; ks++) {
            int kb = ks * 32;
            uint32_t afr[2][4];
#pragma unroll
            for (int mt = 0; mt < 2; mt++) {
                uint32_t ad = abase + (uint32_t)((m0 + mt * 16 + a_row_in) * TROWB + kb + a_koff);
                ldsm4(ad, afr[mt][0], afr[mt][1], afr[mt][2], afr[mt][3]);
            }
            uint32_t bfr[4][4];
#pragma unroll
            for (int pt = 0; pt < 4; pt++) {
                uint32_t bd = bbase + (uint32_t)((n0 + pt * 16 + b_row_in) * TROWB + kb + b_koff);
                ldsm4(bd, bfr[pt][0], bfr[pt][1], bfr[pt][2], bfr[pt][3]);
            }
#pragma unroll
            for (int mt = 0; mt < 2; mt++)
#pragma unroll
                for (int nt = 0; nt < 8; nt++)
                    mma16816(acc[mt][nt], afr[mt], bfr[nt >> 1][(nt & 1) * 2],
                             bfr[nt >> 1][(nt & 1) * 2 + 1]);
        }
    }

    // epilogue: fp16 H store + fused attention-logit dots (this warp's head)
    const float* sAS = (const float*)(smem + OFF_AS);
    const float* sAD = (const float*)(smem + OFF_AD);
    float ss[2][2] = {{0.f, 0.f}, {0.f, 0.f}};
    float dd[2][2] = {{0.f, 0.f}, {0.f, 0.f}};
#pragma unroll
    for (int nt = 0; nt < 8; nt++) {
        int col = n0 + nt * 8 + ((lane & 3) << 1);
        float as0 = sAS[col], as1 = sAS[col + 1];
        float ad0 = sAD[col], ad1 = sAD[col + 1];
#pragma unroll
        for (int mt = 0; mt < 2; mt++) {
            float c0 = acc[mt][nt][0], c1 = acc[mt][nt][1];
            float c2 = acc[mt][nt][2], c3 = acc[mt][nt][3];
            int r0 = row0 + m0 + mt * 16 + (lane >> 2);
            if (r0 < N) *(__half2*)(g_hh + (size_t)r0 * F + col) = __floats2half2_rn(c0, c1);
            if (r0 + 8 < N)
                *(__half2*)(g_hh + (size_t)(r0 + 8) * F + col) = __floats2half2_rn(c2, c3);
            ss[mt][0] += c0 * as0 + c1 * as1;
            ss[mt][1] += c2 * as0 + c3 * as1;
            dd[mt][0] += c0 * ad0 + c1 * ad1;
            dd[mt][1] += c2 * ad0 + c3 * ad1;
        }
    }
#pragma unroll
    for (int mt = 0; mt < 2; mt++)
#pragma unroll
        for (int rh = 0; rh < 2; rh++) {
            ss[mt][rh] += __shfl_xor_sync(0xffffffffu, ss[mt][rh], 1);
            ss[mt][rh] += __shfl_xor_sync(0xffffffffu, ss[mt][rh], 2);
            dd[mt][rh] += __shfl_xor_sync(0xffffffffu, dd[mt][rh], 1);
            dd[mt][rh] += __shfl_xor_sync(0xffffffffu, dd[mt][rh], 2);
        }
    if ((lane & 3) == 0) {
#pragma unroll
        for (int mt = 0; mt < 2; mt++)
#pragma unroll
            for (int rh = 0; rh < 2; rh++) {
                int m = row0 + m0 + mt * 16 + rh * 8 + (lane >> 2);
                if (m < N) {
                    g_als[m * NHEAD + warp_n] = ss[mt][rh];
                    g_ald[m * NHEAD + warp_n] = dd[mt][rh];
                }
            }
    }
}

// ---------------- fused CSR aggregation (fp16 gather, fp32 accumulate) ----------
__global__ void k_aggregate(const float* __restrict__ bias, int residual, int fuse_lin,
                            const float* __restrict__ lin_w, const float* __restrict__ lin_b,
                            float* __restrict__ out, int N) {
    int d = (blockIdx.x * blockDim.x + threadIdx.x) >> 5;
    if (d >= N) return;
    int lane = threadIdx.x & 31;
    int head = lane >> 4;

    float ald = g_ald[d * NHEAD + head];
    int beg = g_rowptr[d], end = g_rowptr[d + 1];

    float4 acc = make_float4(0.f, 0.f, 0.f, 0.f);
    float sum = 0.f;
    const uint2* H2 = (const uint2*)g_hh;

    int j = beg;
    for (; j + 4 <= end; j += 4) {
        int s0 = g_esrc[j], s1 = g_esrc[j + 1], s2 = g_esrc[j + 2], s3 = g_esrc[j + 3];
        float e0 = __expf(leaky(g_als[s0 * NHEAD + head] + ald));
        float e1 = __expf(leaky(g_als[s1 * NHEAD + head] + ald));
        float e2 = __expf(leaky(g_als[s2 * NHEAD + head] + ald));
        float e3 = __expf(leaky(g_als[s3 * NHEAD + head] + ald));
        uint2 r0 = __ldg(H2 + (size_t)s0 * 32 + lane);
        uint2 r1 = __ldg(H2 + (size_t)s1 * 32 + lane);
        uint2 r2 = __ldg(H2 + (size_t)s2 * 32 + lane);
        uint2 r3 = __ldg(H2 + (size_t)s3 * 32 + lane);
        sum += (e0 + e1) + (e2 + e3);
        float2 a0 = __half22float2(*(__half2*)&r0.x), b0 = __half22float2(*(__half2*)&r0.y);
        float2 a1 = __half22float2(*(__half2*)&r1.x), b1 = __half22float2(*(__half2*)&r1.y);
        float2 a2 = __half22float2(*(__half2*)&r2.x), b2 = __half22float2(*(__half2*)&r2.y);
        float2 a3 = __half22float2(*(__half2*)&r3.x), b3 = __half22float2(*(__half2*)&r3.y);
        acc.x += e0 * a0.x + e1 * a1.x + e2 * a2.x + e3 * a3.x;
        acc.y += e0 * a0.y + e1 * a1.y + e2 * a2.y + e3 * a3.y;
        acc.z += e0 * b0.x + e1 * b1.x + e2 * b2.x + e3 * b3.x;
        acc.w += e0 * b0.y + e1 * b1.y + e2 * b2.y + e3 * b3.y;
    }
    for (; j < end; j++) {
        int s = g_esrc[j];
        float ex = __expf(leaky(g_als[s * NHEAD + head] + ald));
        uint2 r = __ldg(H2 + (size_t)s * 32 + lane);
        float2 a = __half22float2(*(__half2*)&r.x), b = __half22float2(*(__half2*)&r.y);
        sum += ex;
        acc.x += ex * a.x; acc.y += ex * a.y;
        acc.z += ex * b.x; acc.w += ex * b.y;
    }

    float inv = 1.f / sum;
    float4 b4 = __ldg(((const float4*)bias) + lane);
    float4 v;
    v.x = acc.x * inv + b4.x; v.y = acc.y * inv + b4.y;
    v.z = acc.z * inv + b4.z; v.w = acc.w * inv + b4.w;
    if (residual) {
        float4 f = ((const float4*)g_feat)[(size_t)d * 32 + lane];
        v.x += f.x; v.y += f.y; v.z += f.z; v.w += f.w;
    }
    v.x = leaky(v.x); v.y = leaky(v.y); v.z = leaky(v.z); v.w = leaky(v.w);
    if (!fuse_lin) {
        ((float4*)g_feat)[(size_t)d * 32 + lane] = v;
    } else {
        float4 wv = __ldg(((const float4*)lin_w) + lane);
        float s = v.x * wv.x + v.y * wv.y + v.z * wv.z + v.w * wv.w;
#pragma unroll
        for (int o = 16; o; o >>= 1) s += __shfl_xor_sync(0xffffffffu, s, o);
        if (lane == 0) out[d] = s + __ldg(lin_b);
    }
}

// ---------------- host ----------------
extern "C" void kernel_launch(void* const* d_in, const int* in_sizes, int n_in,
                              void* d_out, int out_size) {
    const float* x = (const float*)d_in[0];
    const int* ei = (const int*)d_in[1];
    const float* W[3] = {(const float*)d_in[2], (const float*)d_in[6], (const float*)d_in[10]};
    const float* as[3] = {(const float*)d_in[3], (const float*)d_in[7], (const float*)d_in[11]};
    const float* ad[3] = {(const float*)d_in[4], (const float*)d_in[8], (const float*)d_in[12]};
    const float* bs[3] = {(const float*)d_in[5], (const float*)d_in[9], (const float*)d_in[13]};
    const float* lin_w = (const float*)d_in[14];
    const float* lin_b = (const float*)d_in[15];

    int N = in_sizes[0] / F;
    int E = in_sizes[1] / 2;
    int EE = E + N;
    int nb = (N + SCANB - 1) / SCANB;

    static bool init_done = false;
    static cudaStream_t s2;
    static cudaEvent_t ev_fork, ev_gemm1;
    if (!init_done) {
        cudaFuncSetAttribute(k_gemm_tc, cudaFuncAttributeMaxDynamicSharedMemorySize,
                             GEMM_SMEM_TOTAL);
        cudaStreamCreateWithFlags(&s2, cudaStreamNonBlocking);
        cudaEventCreateWithFlags(&ev_fork, cudaEventDisableTiming);
        cudaEventCreateWithFlags(&ev_gemm1, cudaEventDisableTiming);
        init_done = true;
    }

    float* feat_ptr = nullptr;
    cudaGetSymbolAddress((void**)&feat_ptr, g_feat);
    int* cnt_ptr = nullptr;
    cudaGetSymbolAddress((void**)&cnt_ptr, g_cnt);
    __nv_bfloat16* wth_ptr = nullptr;
    cudaGetSymbolAddress((void**)&wth_ptr, g_wth);
    __nv_bfloat16* wtl_ptr = nullptr;
    cudaGetSymbolAddress((void**)&wtl_ptr, g_wtl);

    const int TB = 256;
    int gemm_blocks = (N + TM - 1) / TM;
    int warpN_blocks = (N * 32 + TB - 1) / TB;
    int edge4_blocks = ((EE + 3) / 4 + TB - 1) / TB;
    int prep_blocks = (3 * F * F + TB - 1) / TB;

    // ---- fork: W prep + layer-1 GEMM on s2, CSR build on stream 0 ----
    cudaEventRecord(ev_fork, 0);
    cudaStreamWaitEvent(s2, ev_fork, 0);
    k_prep_w3<<<prep_blocks, TB, 0, s2>>>(W[0], W[1], W[2]);
    k_gemm_tc<<<gemm_blocks, 256, GEMM_SMEM_TOTAL, s2>>>(
        x, wth_ptr, wtl_ptr, as[0], ad[0], N);
    cudaEventRecord(ev_gemm1, s2);

    cudaMemsetAsync(cnt_ptr, 0, N * sizeof(int));
    k_build_hist<<<edge4_blocks, TB>>>(ei, E, N);
    k_scan1<<<nb, SCANB>>>(N);
    k_scan23<<<nb, SCANB>>>(N, EE, nb);
    k_fill<<<edge4_blocks, TB>>>(ei, E, N);

    // ---- join, then the rest on stream 0 ----
    cudaStreamWaitEvent(0, ev_gemm1, 0);
    k_aggregate<<<warpN_blocks, TB>>>(bs[0], 0, 0, lin_w, lin_b, (float*)d_out, N);

    for (int l = 1; l < 3; l++) {
        k_gemm_tc<<<gemm_blocks, 256, GEMM_SMEM_TOTAL>>>(
            feat_ptr, wth_ptr + (size_t)l * F * F, wtl_ptr + (size_t)l * F * F,
            as[l], ad[l], N);
        k_aggregate<<<warpN_blocks, TB>>>(bs[l], 1, l == 2, lin_w, lin_b,
                                          (float*)d_out, N);
    }
}